// round 4
// baseline (speedup 1.0000x reference)
#include <cuda_runtime.h>

#define Nn   50000
#define Ee   800000
#define DIN  128
#define DH   256
#define DOUT 128
#define BNEPS 1e-5f

// ---------------- scratch (device globals: allocation-free) ----------------
__device__ int   g_is64;
__device__ __align__(256) int   g_src [Ee];
__device__ __align__(256) int   g_dst [Ee];
__device__ __align__(256) int   g_nb_src[Ee];
__device__ __align__(256) float g_nb_nrm[Ee];
__device__ __align__(256) int   g_rowptr[Nn + 1];
__device__ __align__(256) int   g_cursor[Nn];
__device__ __align__(256) int   g_cnt [Nn];
__device__ __align__(256) float g_dinv[Nn];
__device__ __align__(256) float g_bufA[(size_t)Nn * DH];
__device__ __align__(256) float g_bufB[(size_t)Nn * DH];
__device__ __align__(256) float g_bufC[(size_t)Nn * DH];
__device__ __align__(256) float g_sum  [DH];
__device__ __align__(256) float g_sumsq[DH];
__device__ __align__(256) float g_scale[DH];
__device__ __align__(256) float g_shift[DH];

// ---------------- edge-index dtype detect + convert ----------------
__global__ void k_detect(const uint2* __restrict__ ei) {
    if (threadIdx.x == 0 && blockIdx.x == 0) {
        int is64 = 1;
        for (int i = 0; i < 64; i++)
            if (ei[i].y != 0u) { is64 = 0; break; }
        g_is64 = is64;
    }
}

__global__ void k_convert(const void* __restrict__ ei) {
    int e = blockIdx.x * blockDim.x + threadIdx.x;
    if (e >= Ee) return;
    int s, d;
    if (g_is64) {
        const long long* p = (const long long*)ei;
        s = (int)p[e];
        d = (int)p[e + Ee];
    } else {
        const int* p = (const int*)ei;
        s = p[e];
        d = p[e + Ee];
    }
    g_src[e] = min(max(s, 0), Nn - 1);
    g_dst[e] = min(max(d, 0), Nn - 1);
}

// ---------------- degree count / CSR build ----------------
__global__ void k_cnt_zero() {
    int i = blockIdx.x * blockDim.x + threadIdx.x;
    if (i < Nn) g_cnt[i] = 0;
}

__global__ void k_count() {
    int e = blockIdx.x * blockDim.x + threadIdx.x;
    if (e < Ee) atomicAdd(&g_cnt[g_dst[e]], 1);
}

__global__ void k_dinv() {
    int i = blockIdx.x * blockDim.x + threadIdx.x;
    if (i < Nn) g_dinv[i] = rsqrtf((float)(g_cnt[i] + 1));  // +1 self loop
}

// single-block exclusive scan over g_cnt -> g_rowptr / g_cursor (1024 thr)
__global__ void k_scan() {
    __shared__ int sh[1024];
    const int T = 1024;
    const int chunk = (Nn + T - 1) / T;   // 49
    int tid  = threadIdx.x;
    int base = tid * chunk;
    int s = 0;
#pragma unroll 4
    for (int j = 0; j < chunk; j++) {
        int i = base + j;
        if (i < Nn) s += g_cnt[i];
    }
    sh[tid] = s;
    __syncthreads();
    // Hillis-Steele inclusive scan
    for (int off = 1; off < T; off <<= 1) {
        int v = (tid >= off) ? sh[tid - off] : 0;
        __syncthreads();
        sh[tid] += v;
        __syncthreads();
    }
    int run = sh[tid] - s;   // exclusive prefix of this thread's chunk
    for (int j = 0; j < chunk; j++) {
        int i = base + j;
        if (i < Nn) {
            g_rowptr[i] = run;
            g_cursor[i] = run;
            run += g_cnt[i];
        }
    }
    if (tid == 0) g_rowptr[Nn] = Ee;
}

__global__ void k_fill() {
    int e = blockIdx.x * blockDim.x + threadIdx.x;
    if (e >= Ee) return;
    int s = g_src[e];
    int d = g_dst[e];
    int pos = atomicAdd(&g_cursor[d], 1);
    g_nb_src[pos] = s;
    g_nb_nrm[pos] = g_dinv[s] * g_dinv[d];
}

// ---------------- gather aggregation: one warp per node ----------------
// out[n] = dinv[n]^2 * in[n] (+ b2 + x if FINAL) + sum_{e in CSR(n)} nrm_e * in[src_e]
template<int F, bool FINAL>
__global__ void __launch_bounds__(256)
k_gather(const float* __restrict__ in,
         const float* __restrict__ x,
         const float* __restrict__ b2,
         float* __restrict__ out) {
    int n = (blockIdx.x * blockDim.x + threadIdx.x) >> 5;
    if (n >= Nn) return;
    int lane = threadIdx.x & 31;
    constexpr int V = F / 128;           // float4 chunks per lane (1 or 2)

    float di = g_dinv[n];
    float s2 = di * di;

    float4 acc[V];
    const float4* self = (const float4*)(in + (size_t)n * F);
#pragma unroll
    for (int v = 0; v < V; v++) {
        float4 t = __ldg(&self[lane + 32 * v]);
        acc[v] = make_float4(t.x * s2, t.y * s2, t.z * s2, t.w * s2);
    }
    if (FINAL) {
        const float4* xr = (const float4*)(x + (size_t)n * F);
#pragma unroll
        for (int v = 0; v < V; v++) {
            float4 xx = __ldg(&xr[lane + 32 * v]);
            float4 bb = __ldg(&((const float4*)b2)[lane + 32 * v]);
            acc[v].x += xx.x + bb.x;
            acc[v].y += xx.y + bb.y;
            acc[v].z += xx.z + bb.z;
            acc[v].w += xx.w + bb.w;
        }
    }

    int beg = g_rowptr[n];
    int end = g_rowptr[n + 1];
    for (int e = beg; e < end; e++) {
        int   s = g_nb_src[e];
        float w = g_nb_nrm[e];
        const float4* r = (const float4*)(in + (size_t)s * F);
#pragma unroll
        for (int v = 0; v < V; v++) {
            float4 t = __ldg(&r[lane + 32 * v]);
            acc[v].x = fmaf(t.x, w, acc[v].x);
            acc[v].y = fmaf(t.y, w, acc[v].y);
            acc[v].z = fmaf(t.z, w, acc[v].z);
            acc[v].w = fmaf(t.w, w, acc[v].w);
        }
    }

    float4* o = (float4*)(out + (size_t)n * F);
#pragma unroll
    for (int v = 0; v < V; v++) o[lane + 32 * v] = acc[v];
}

// ---------------- BatchNorm ----------------
__global__ void k_bn_zero() {
    int f = threadIdx.x;
    if (f < DH) { g_sum[f] = 0.0f; g_sumsq[f] = 0.0f; }
}

template<int F, int RPB>
__global__ void k_bn_stats(const float* __restrict__ h) {
    int f  = threadIdx.x;
    int r0 = blockIdx.x * RPB;
    int r1 = min(r0 + RPB, Nn);
    float s = 0.0f, ss = 0.0f;
    for (int r = r0; r < r1; ++r) {
        float v = h[(size_t)r * F + f];
        s += v; ss += v * v;
    }
    atomicAdd(&g_sum[f],   s);
    atomicAdd(&g_sumsq[f], ss);
}

__global__ void k_bn_final(const float* __restrict__ g, const float* __restrict__ be) {
    int f = threadIdx.x;
    if (f >= DH) return;
    float mu  = g_sum[f]   * (1.0f / Nn);
    float var = g_sumsq[f] * (1.0f / Nn) - mu * mu;
    float sc  = g[f] * rsqrtf(var + BNEPS);
    g_scale[f] = sc;
    g_shift[f] = be[f] - mu * sc;
}

template<bool RES>
__global__ void k_bn_apply(const float* __restrict__ h,
                           const float* __restrict__ res,
                           float* __restrict__ out) {
    int idx = blockIdx.x * blockDim.x + threadIdx.x;
    if (idx >= Nn * (DH / 4)) return;
    int f4 = idx & (DH / 4 - 1);
    float4 v  = ((const float4*)h)[idx];
    float4 sc = ((const float4*)g_scale)[f4];
    float4 sh = ((const float4*)g_shift)[f4];
    v.x = fmaxf(v.x * sc.x + sh.x, 0.0f);
    v.y = fmaxf(v.y * sc.y + sh.y, 0.0f);
    v.z = fmaxf(v.z * sc.z + sh.z, 0.0f);
    v.w = fmaxf(v.w * sc.w + sh.w, 0.0f);
    if (RES) {
        float4 r = ((const float4*)res)[idx];
        v.x += r.x; v.y += r.y; v.z += r.z; v.w += r.w;
    }
    ((float4*)out)[idx] = v;
}

// ---------------- SGEMM: C[MxNc] = A[MxK] * B[KxNc], row-major ----------------
__global__ void __launch_bounds__(256)
k_sgemm(int M, int Nc, int K,
        const float* __restrict__ A, const float* __restrict__ B, float* __restrict__ C) {
    constexpr int BM = 128, BN = 128, BK = 8, TM = 8, TN = 8;
    __shared__ float As[BK][BM];
    __shared__ float Bs[BK][BN];
    int tid  = threadIdx.x;
    int brow = blockIdx.y * BM;
    int bcol = blockIdx.x * BN;
    int trow = (tid / (BN / TN)) * TM;
    int tcol = (tid % (BN / TN)) * TN;

    int aRow = tid >> 1;
    int aCol = (tid & 1) * 4;
    int bRow = tid >> 5;
    int bCol = (tid & 31) * 4;

    float acc[TM][TN];
#pragma unroll
    for (int i = 0; i < TM; i++)
#pragma unroll
        for (int j = 0; j < TN; j++) acc[i][j] = 0.0f;

    for (int k0 = 0; k0 < K; k0 += BK) {
        float4 a4;
        int gr = brow + aRow;
        if (gr < M) a4 = *(const float4*)(A + (size_t)gr * K + k0 + aCol);
        else        a4 = make_float4(0.f, 0.f, 0.f, 0.f);
        As[aCol + 0][aRow] = a4.x;
        As[aCol + 1][aRow] = a4.y;
        As[aCol + 2][aRow] = a4.z;
        As[aCol + 3][aRow] = a4.w;
        *(float4*)&Bs[bRow][bCol] =
            *(const float4*)(B + (size_t)(k0 + bRow) * Nc + bcol + bCol);
        __syncthreads();
#pragma unroll
        for (int kk = 0; kk < BK; kk++) {
            float4 a0 = *(float4*)&As[kk][trow];
            float4 a1 = *(float4*)&As[kk][trow + 4];
            float4 b0 = *(float4*)&Bs[kk][tcol];
            float4 b1 = *(float4*)&Bs[kk][tcol + 4];
            float ar[TM] = {a0.x, a0.y, a0.z, a0.w, a1.x, a1.y, a1.z, a1.w};
            float br[TN] = {b0.x, b0.y, b0.z, b0.w, b1.x, b1.y, b1.z, b1.w};
#pragma unroll
            for (int i = 0; i < TM; i++)
#pragma unroll
                for (int j = 0; j < TN; j++)
                    acc[i][j] = fmaf(ar[i], br[j], acc[i][j]);
        }
        __syncthreads();
    }
#pragma unroll
    for (int i = 0; i < TM; i++) {
        int gr = brow + trow + i;
        if (gr >= M) continue;
#pragma unroll
        for (int j = 0; j < TN; j += 4) {
            float4 v = make_float4(acc[i][j], acc[i][j + 1], acc[i][j + 2], acc[i][j + 3]);
            *(float4*)(C + (size_t)gr * Nc + bcol + tcol + j) = v;
        }
    }
}

// ---------------- launch ----------------
extern "C" void kernel_launch(void* const* d_in, const int* in_sizes, int n_in,
                              void* d_out, int out_size) {
    const float* x  = (const float*)d_in[0];
    const void*  ei = d_in[1];
    const float* W0 = (const float*)d_in[2];
    // b0 = d_in[3]  (cancels exactly through BatchNorm)
    const float* g0  = (const float*)d_in[4];
    const float* be0 = (const float*)d_in[5];
    const float* W1  = (const float*)d_in[6];
    // b1 = d_in[7]  (cancels exactly through BatchNorm)
    const float* g1  = (const float*)d_in[8];
    const float* be1 = (const float*)d_in[9];
    const float* W2  = (const float*)d_in[10];
    const float* b2  = (const float*)d_in[11];
    float* out = (float*)d_out;

    float *bufA, *bufB, *bufC;
    cudaGetSymbolAddress((void**)&bufA, g_bufA);
    cudaGetSymbolAddress((void**)&bufB, g_bufB);
    cudaGetSymbolAddress((void**)&bufC, g_bufC);

    const int TB = 256;
    int gridE1 = (Ee + TB - 1) / TB;
    int gridN1 = (Nn + TB - 1) / TB;

    // edge-index dtype detect + convert + CSR build + normalization
    k_detect  <<<1, 32>>>((const uint2*)ei);
    k_convert <<<gridE1, TB>>>(ei);
    k_cnt_zero<<<gridN1, TB>>>();
    k_count   <<<gridE1, TB>>>();
    k_dinv    <<<gridN1, TB>>>();
    k_scan    <<<1, 1024>>>();
    k_fill    <<<gridE1, TB>>>();

    int gridN256 = (Nn * (DH / 4) + TB - 1) / TB;
    int gridW    = (Nn * 32 + TB - 1) / TB;          // 1 warp / node

    // ---- layer 0: aggregate-first on x (128-dim) ----
    k_gather<DIN, false><<<gridW, TB>>>(x, nullptr, nullptr, bufA);
    {
        dim3 g(DH / 128, (Nn + 127) / 128);
        k_sgemm<<<g, 256>>>(Nn, DH, DIN, bufA, W0, bufB);     // H0 = (A x) W0
    }
    k_bn_zero<<<1, 256>>>();
    k_bn_stats<DH, 64><<<(Nn + 63) / 64, DH>>>(bufB);
    k_bn_final<<<1, 256>>>(g0, be0);
    k_bn_apply<false><<<gridN256, TB>>>(bufB, nullptr, bufA);  // h1 -> bufA

    // ---- layer 1: aggregate-first on h1 (256-dim) ----
    k_gather<DH, false><<<gridW, TB>>>(bufA, nullptr, nullptr, bufC);
    {
        dim3 g(DH / 128, (Nn + 127) / 128);
        k_sgemm<<<g, 256>>>(Nn, DH, DH, bufC, W1, bufB);       // M1 = (A h1) W1
    }
    k_bn_zero<<<1, 256>>>();
    k_bn_stats<DH, 64><<<(Nn + 63) / 64, DH>>>(bufB);
    k_bn_final<<<1, 256>>>(g1, be1);
    k_bn_apply<true><<<gridN256, TB>>>(bufB, bufA, bufC);      // h2 = relu(bn)+h1 -> bufC

    // ---- layer 2: transform-first, epilogue fused into gather ----
    {
        dim3 g(DOUT / 128, (Nn + 127) / 128);
        k_sgemm<<<g, 256>>>(Nn, DOUT, DH, bufC, W2, bufA);     // M2 = h2 W2
    }
    k_gather<DOUT, true><<<gridW, TB>>>(bufA, x, b2, out);     // out = M2*dinv^2+b2+x+Σ
}

// round 6
// speedup vs baseline: 1.3800x; 1.3800x over previous
#include <cuda_runtime.h>
#include <cuda_bf16.h>
#include <cstdint>

#define Nn   50000
#define NPAD 50048
#define Ee   800000
#define DIN  128
#define DH   256
#define DOUT 128
#define BNEPS 1e-5f

// ---------------- scratch (device globals: allocation-free) ----------------
__device__ int   g_is64;
__device__ __align__(256) int   g_src [Ee];
__device__ __align__(256) int   g_dst [Ee];
__device__ __align__(256) float g_nrm [Ee];
__device__ __align__(256) float g_deg [Nn];
__device__ __align__(256) float g_dinv[Nn];
__device__ __align__(256) float g_bufA[(size_t)Nn * DH];
__device__ __align__(256) float g_bufB[(size_t)Nn * DH];
__device__ __align__(256) float g_bufC[(size_t)Nn * DH];
__device__ __align__(256) __nv_bfloat16 g_A16[(size_t)NPAD * 3 * DH]; // [rows, 3K], K<=256
__device__ __align__(256) __nv_bfloat16 g_B16[(size_t)DH * 3 * DH];   // [Nc, 3K]
__device__ __align__(256) float g_sum  [DH];
__device__ __align__(256) float g_sumsq[DH];
__device__ __align__(256) float g_scale[DH];
__device__ __align__(256) float g_shift[DH];

__device__ __forceinline__ uint32_t smem_u32(const void* p) {
    uint32_t a;
    asm("{ .reg .u64 t; cvta.to.shared.u64 t, %1; cvt.u32.u64 %0, t; }" : "=r"(a) : "l"(p));
    return a;
}

// ---------------- edge-index dtype detect + convert ----------------
__global__ void k_detect(const uint2* __restrict__ ei) {
    if (threadIdx.x == 0 && blockIdx.x == 0) {
        int is64 = 1;
        for (int i = 0; i < 64; i++)
            if (ei[i].y != 0u) { is64 = 0; break; }
        g_is64 = is64;
    }
}

__global__ void k_convert(const void* __restrict__ ei) {
    int e = blockIdx.x * blockDim.x + threadIdx.x;
    if (e >= Ee) return;
    int s, d;
    if (g_is64) {
        const long long* p = (const long long*)ei;
        s = (int)p[e];
        d = (int)p[e + Ee];
    } else {
        const int* p = (const int*)ei;
        s = p[e];
        d = p[e + Ee];
    }
    g_src[e] = min(max(s, 0), Nn - 1);
    g_dst[e] = min(max(d, 0), Nn - 1);
}

// ---------------- degree / normalization ----------------
__global__ void k_deg_init() {
    int i = blockIdx.x * blockDim.x + threadIdx.x;
    if (i < Nn) g_deg[i] = 1.0f;
}
__global__ void k_deg_acc() {
    int e = blockIdx.x * blockDim.x + threadIdx.x;
    if (e < Ee) atomicAdd(&g_deg[g_dst[e]], 1.0f);
}
__global__ void k_dinv() {
    int i = blockIdx.x * blockDim.x + threadIdx.x;
    if (i < Nn) g_dinv[i] = rsqrtf(g_deg[i]);
}
__global__ void k_edge_nrm() {
    int e = blockIdx.x * blockDim.x + threadIdx.x;
    if (e < Ee) g_nrm[e] = g_dinv[g_src[e]] * g_dinv[g_dst[e]];
}

// ---------------- aggregation ----------------
template<int F>
__global__ void k_self_init(const float* __restrict__ in, float* __restrict__ out) {
    int idx = blockIdx.x * blockDim.x + threadIdx.x;
    if (idx >= Nn * (F / 4)) return;
    int row = idx / (F / 4);
    float s = g_dinv[row]; s = s * s;
    float4 v = ((const float4*)in)[idx];
    v.x *= s; v.y *= s; v.z *= s; v.w *= s;
    ((float4*)out)[idx] = v;
}

template<int F>
__global__ void k_scatter(const float* __restrict__ in, float* __restrict__ out) {
    int e = (blockIdx.x * blockDim.x + threadIdx.x) >> 5;
    if (e >= Ee) return;
    int lane = threadIdx.x & 31;
    int s = g_src[e];
    int d = g_dst[e];
    float nrm = g_nrm[e];
    const float* rin  = in  + (size_t)s * F;
    float*       rout = out + (size_t)d * F;
#pragma unroll
    for (int j = lane; j < F; j += 32)
        atomicAdd(&rout[j], __ldg(&rin[j]) * nrm);
}

// ---------------- BatchNorm ----------------
__global__ void k_bn_zero() {
    int f = threadIdx.x;
    if (f < DH) { g_sum[f] = 0.0f; g_sumsq[f] = 0.0f; }
}

template<int F, int RPB>
__global__ void k_bn_stats(const float* __restrict__ h) {
    int f  = threadIdx.x;
    int r0 = blockIdx.x * RPB;
    int r1 = min(r0 + RPB, Nn);
    float s = 0.0f, ss = 0.0f;
    for (int r = r0; r < r1; ++r) {
        float v = h[(size_t)r * F + f];
        s += v; ss += v * v;
    }
    atomicAdd(&g_sum[f],   s);
    atomicAdd(&g_sumsq[f], ss);
}

__global__ void k_bn_final(const float* __restrict__ g, const float* __restrict__ be) {
    int f = threadIdx.x;
    if (f >= DH) return;
    float mu  = g_sum[f]   * (1.0f / Nn);
    float var = g_sumsq[f] * (1.0f / Nn) - mu * mu;
    float sc  = g[f] * rsqrtf(var + BNEPS);
    g_scale[f] = sc;
    g_shift[f] = be[f] - mu * sc;
}

template<bool RES>
__global__ void k_bn_apply(const float* __restrict__ h,
                           const float* __restrict__ res,
                           float* __restrict__ out) {
    int idx = blockIdx.x * blockDim.x + threadIdx.x;
    if (idx >= Nn * (DH / 4)) return;
    int f4 = idx & (DH / 4 - 1);
    float4 v  = ((const float4*)h)[idx];
    float4 sc = ((const float4*)g_scale)[f4];
    float4 sh = ((const float4*)g_shift)[f4];
    v.x = fmaxf(v.x * sc.x + sh.x, 0.0f);
    v.y = fmaxf(v.y * sc.y + sh.y, 0.0f);
    v.z = fmaxf(v.z * sc.z + sh.z, 0.0f);
    v.w = fmaxf(v.w * sc.w + sh.w, 0.0f);
    if (RES) {
        float4 r = ((const float4*)res)[idx];
        v.x += r.x; v.y += r.y; v.z += r.z; v.w += r.w;
    }
    ((float4*)out)[idx] = v;
}

// ---------------- final epilogue init: M2*dinv^2 + b2 + x ----------------
__global__ void k_final_init(const float* __restrict__ m2,
                             const float* __restrict__ x,
                             const float* __restrict__ b2,
                             float* __restrict__ out) {
    int idx = blockIdx.x * blockDim.x + threadIdx.x;
    if (idx >= Nn * (DOUT / 4)) return;
    int row = idx / (DOUT / 4);
    int c4  = idx & (DOUT / 4 - 1);
    float s = g_dinv[row]; s = s * s;
    float4 m  = ((const float4*)m2)[idx];
    float4 xx = ((const float4*)x)[idx];
    float4 b  = ((const float4*)b2)[c4];
    m.x = m.x * s + xx.x + b.x;
    m.y = m.y * s + xx.y + b.y;
    m.z = m.z * s + xx.z + b.z;
    m.w = m.w * s + xx.w + b.w;
    ((float4*)out)[idx] = m;
}

// ---------------- fp32 -> bf16 hi/lo split conversion ----------------
// A layout: [rows, 3F] = [Ah | Al | Ah]; rows >= Nn are zero-padded
template<int F>
__global__ void k_cvtA(const float* __restrict__ in, __nv_bfloat16* __restrict__ out) {
    int idx = blockIdx.x * blockDim.x + threadIdx.x;   // over NPAD*F
    if (idx >= NPAD * F) return;
    int row = idx / F, col = idx - row * F;
    float v = (row < Nn) ? in[(size_t)row * F + col] : 0.0f;
    __nv_bfloat16 h = __float2bfloat16(v);
    __nv_bfloat16 l = __float2bfloat16(v - __bfloat162float(h));
    size_t base = (size_t)row * (3 * F);
    out[base + col]         = h;
    out[base + F + col]     = l;
    out[base + 2 * F + col] = h;
}

// B layout (transposed weights): [Nc, 3K] = [Bh | Bh | Bl], Bt[n][k] = W[k][n]
__global__ void k_cvtB(const float* __restrict__ W, __nv_bfloat16* __restrict__ out,
                       int K, int Nc) {
    int idx = blockIdx.x * blockDim.x + threadIdx.x;   // over K*Nc
    if (idx >= K * Nc) return;
    int k = idx / Nc, n = idx - k * Nc;
    float v = W[idx];
    __nv_bfloat16 h = __float2bfloat16(v);
    __nv_bfloat16 l = __float2bfloat16(v - __bfloat162float(h));
    size_t base = (size_t)n * (3 * K);
    out[base + k]         = h;
    out[base + K + k]     = h;
    out[base + 2 * K + k] = l;
}

// ---------------- mma.sync bf16 GEMM: C[M x Nc] = A16[M,K3] * B16[Nc,K3]^T ----
// CTA tile 128x128, 8 warps (2x4), warp tile 64x32, BK=32, smem rows padded to 40.
#define LDP 40
template<int K3>
__global__ void __launch_bounds__(256)
k_gemm16(const __nv_bfloat16* __restrict__ A, const __nv_bfloat16* __restrict__ B,
         float* __restrict__ C, int Nc) {
    __shared__ __align__(16) __nv_bfloat16 sA[128][LDP];
    __shared__ __align__(16) __nv_bfloat16 sB[128][LDP];

    int tid  = threadIdx.x;
    int wid  = tid >> 5;
    int lane = tid & 31;
    int brow = blockIdx.y * 128;
    int bcol = blockIdx.x * 128;

    int warp_m = wid >> 2;        // 0..1 -> 64-row slab
    int warp_n = wid & 3;         // 0..3 -> 32-col slab
    int m_base = warp_m * 64;
    int n_base = warp_n * 32;

    // ldmatrix lane addressing (constant per lane)
    int aRow  = m_base + (lane & 15);
    int aColH = (lane >> 4) * 8;
    int bRow  = n_base + (lane & 7);
    int bColH = ((lane >> 3) & 1) * 8;

    float acc[4][4][4];
#pragma unroll
    for (int i = 0; i < 4; i++)
#pragma unroll
        for (int j = 0; j < 4; j++)
#pragma unroll
            for (int q = 0; q < 4; q++) acc[i][j][q] = 0.0f;

    // global load mapping: 512 uint4 per operand per k-tile, 2 per thread
    int ldRow = tid >> 2;          // 0..63
    int ldChk = (tid & 3) * 8;     // bf16 col offset 0,8,16,24

    constexpr int NCHUNK = K3 / 32;
    for (int c = 0; c < NCHUNK; c++) {
        int kc = c * 32;
#pragma unroll
        for (int half = 0; half < 2; half++) {
            int r = ldRow + half * 64;
            *(uint4*)&sA[r][ldChk] =
                *(const uint4*)(A + (size_t)(brow + r) * K3 + kc + ldChk);
            *(uint4*)&sB[r][ldChk] =
                *(const uint4*)(B + (size_t)(bcol + r) * K3 + kc + ldChk);
        }
        __syncthreads();

#pragma unroll
        for (int ks = 0; ks < 2; ks++) {
            uint32_t af[4][4], bf[4][2];
#pragma unroll
            for (int i = 0; i < 4; i++) {
                uint32_t addr = smem_u32(&sA[aRow + i * 16][ks * 16 + aColH]);
                asm volatile("ldmatrix.sync.aligned.m8n8.x4.shared.b16 {%0,%1,%2,%3}, [%4];"
                             : "=r"(af[i][0]), "=r"(af[i][1]), "=r"(af[i][2]), "=r"(af[i][3])
                             : "r"(addr));
            }
#pragma unroll
            for (int j = 0; j < 4; j++) {
                uint32_t addr = smem_u32(&sB[bRow + j * 8][ks * 16 + bColH]);
                asm volatile("ldmatrix.sync.aligned.m8n8.x2.shared.b16 {%0,%1}, [%2];"
                             : "=r"(bf[j][0]), "=r"(bf[j][1]) : "r"(addr));
            }
#pragma unroll
            for (int i = 0; i < 4; i++)
#pragma unroll
                for (int j = 0; j < 4; j++) {
                    asm volatile(
                        "mma.sync.aligned.m16n8k16.row.col.f32.bf16.bf16.f32 "
                        "{%0,%1,%2,%3}, {%4,%5,%6,%7}, {%8,%9}, {%0,%1,%2,%3};"
                        : "+f"(acc[i][j][0]), "+f"(acc[i][j][1]),
                          "+f"(acc[i][j][2]), "+f"(acc[i][j][3])
                        : "r"(af[i][0]), "r"(af[i][1]), "r"(af[i][2]), "r"(af[i][3]),
                          "r"(bf[j][0]), "r"(bf[j][1]));
                }
        }
        __syncthreads();
    }

    // epilogue: lane owns rows (lane/4, +8), cols (lane%4)*2
#pragma unroll
    for (int i = 0; i < 4; i++) {
        int row0 = brow + m_base + i * 16 + (lane >> 2);
        int row1 = row0 + 8;
#pragma unroll
        for (int j = 0; j < 4; j++) {
            int col = bcol + n_base + j * 8 + (lane & 3) * 2;
            if (row0 < Nn)
                *(float2*)(C + (size_t)row0 * Nc + col) =
                    make_float2(acc[i][j][0], acc[i][j][1]);
            if (row1 < Nn)
                *(float2*)(C + (size_t)row1 * Nc + col) =
                    make_float2(acc[i][j][2], acc[i][j][3]);
        }
    }
}

// ---------------- launch ----------------
extern "C" void kernel_launch(void* const* d_in, const int* in_sizes, int n_in,
                              void* d_out, int out_size) {
    const float* x  = (const float*)d_in[0];
    const void*  ei = d_in[1];
    const float* W0 = (const float*)d_in[2];
    // b0 = d_in[3]  (cancels exactly through BatchNorm)
    const float* g0  = (const float*)d_in[4];
    const float* be0 = (const float*)d_in[5];
    const float* W1  = (const float*)d_in[6];
    // b1 = d_in[7]  (cancels exactly through BatchNorm)
    const float* g1  = (const float*)d_in[8];
    const float* be1 = (const float*)d_in[9];
    const float* W2  = (const float*)d_in[10];
    const float* b2  = (const float*)d_in[11];
    float* out = (float*)d_out;

    float *bufA, *bufB, *bufC;
    __nv_bfloat16 *A16, *B16;
    cudaGetSymbolAddress((void**)&bufA, g_bufA);
    cudaGetSymbolAddress((void**)&bufB, g_bufB);
    cudaGetSymbolAddress((void**)&bufC, g_bufC);
    cudaGetSymbolAddress((void**)&A16,  g_A16);
    cudaGetSymbolAddress((void**)&B16,  g_B16);

    const int TB = 256;
    int gridE1 = (Ee + TB - 1) / TB;
    int gridN1 = (Nn + TB - 1) / TB;

    k_detect  <<<1, 32>>>((const uint2*)ei);
    k_convert <<<gridE1, TB>>>(ei);
    k_deg_init<<<gridN1, TB>>>();
    k_deg_acc <<<gridE1, TB>>>();
    k_dinv    <<<gridN1, TB>>>();
    k_edge_nrm<<<gridE1, TB>>>();

    int gridN128 = (Nn * (DIN / 4) + TB - 1) / TB;
    int gridN256 = (Nn * (DH  / 4) + TB - 1) / TB;
    int gridE    = (Ee * 32 + TB - 1) / TB;
    int gridCvt128 = (NPAD * DIN + TB - 1) / TB;
    int gridCvt256 = (NPAD * DH  + TB - 1) / TB;
    dim3 gemmG2(2, NPAD / 128);   // Nc=256
    dim3 gemmG1(1, NPAD / 128);   // Nc=128

    // ---- layer 0: aggregate-first on x (K=128 -> K3=384) ----
    k_self_init<DIN><<<gridN128, TB>>>(x, bufA);
    k_scatter<DIN>  <<<gridE, TB>>>(x, bufA);
    k_cvtB<<<(DIN * DH + TB - 1) / TB, TB>>>(W0, B16, DIN, DH);
    k_cvtA<DIN><<<gridCvt128, TB>>>(bufA, A16);
    k_gemm16<3 * DIN><<<gemmG2, 256>>>(A16, B16, bufB, DH);   // H0 = (A x) W0
    k_bn_zero<<<1, 256>>>();
    k_bn_stats<DH, 64><<<(Nn + 63) / 64, DH>>>(bufB);
    k_bn_final<<<1, 256>>>(g0, be0);
    k_bn_apply<false><<<gridN256, TB>>>(bufB, nullptr, bufA);  // h1 -> bufA

    // ---- layer 1 (K=256 -> K3=768) ----
    k_self_init<DH><<<gridN256, TB>>>(bufA, bufC);
    k_scatter<DH>  <<<gridE, TB>>>(bufA, bufC);
    k_cvtB<<<(DH * DH + TB - 1) / TB, TB>>>(W1, B16, DH, DH);
    k_cvtA<DH><<<gridCvt256, TB>>>(bufC, A16);
    k_gemm16<3 * DH><<<gemmG2, 256>>>(A16, B16, bufB, DH);     // M1 = (A h1) W1
    k_bn_zero<<<1, 256>>>();
    k_bn_stats<DH, 64><<<(Nn + 63) / 64, DH>>>(bufB);
    k_bn_final<<<1, 256>>>(g1, be1);
    k_bn_apply<true><<<gridN256, TB>>>(bufB, bufA, bufC);      // h2 -> bufC

    // ---- layer 2: transform-first (K=256 -> K3=768), scatter epilogue ----
    k_cvtB<<<(DH * DOUT + TB - 1) / TB, TB>>>(W2, B16, DH, DOUT);
    k_cvtA<DH><<<gridCvt256, TB>>>(bufC, A16);
    k_gemm16<3 * DH><<<gemmG1, 256>>>(A16, B16, bufA, DOUT);   // M2 = h2 W2
    k_final_init<<<gridN128, TB>>>(bufA, x, b2, out);          // M2*dinv^2 + b2 + x
    k_scatter<DOUT><<<gridE, TB>>>(bufA, out);
}

// round 7
// speedup vs baseline: 1.7139x; 1.2419x over previous
#include <cuda_runtime.h>
#include <cuda_bf16.h>
#include <cstdint>

#define Nn   50000
#define NPAD 50048
#define Ee   800000
#define DIN  128
#define DH   256
#define DOUT 128
#define BNEPS 1e-5f

// ---------------- scratch (device globals: allocation-free) ----------------
__device__ int   g_is64;
__device__ __align__(256) int   g_src [Ee];
__device__ __align__(256) int   g_dst [Ee];
__device__ __align__(256) float g_nrm [Ee];
__device__ __align__(256) float g_deg [Nn];
__device__ __align__(256) float g_dinv[Nn];
__device__ __align__(256) float g_bufA[(size_t)Nn * DH];
__device__ __align__(256) float g_bufB[(size_t)Nn * DH];
__device__ __align__(256) float g_bufC[(size_t)Nn * DH];
__device__ __align__(256) __nv_bfloat16 g_B16[(size_t)2 * DH * DH];  // [Bh plane | Bl plane]
__device__ __align__(256) float g_sum  [DH];
__device__ __align__(256) float g_sumsq[DH];
__device__ __align__(256) float g_scale[DH];
__device__ __align__(256) float g_shift[DH];

__device__ __forceinline__ uint32_t smem_u32(const void* p) {
    uint32_t a;
    asm("{ .reg .u64 t; cvta.to.shared.u64 t, %1; cvt.u32.u64 %0, t; }" : "=r"(a) : "l"(p));
    return a;
}

#define MMA16816(d, a, b)                                                     \
    asm volatile("mma.sync.aligned.m16n8k16.row.col.f32.bf16.bf16.f32 "       \
                 "{%0,%1,%2,%3}, {%4,%5,%6,%7}, {%8,%9}, {%0,%1,%2,%3};"      \
                 : "+f"((d)[0]), "+f"((d)[1]), "+f"((d)[2]), "+f"((d)[3])     \
                 : "r"((a)[0]), "r"((a)[1]), "r"((a)[2]), "r"((a)[3]),        \
                   "r"((b)[0]), "r"((b)[1]))

#define LDSM_X4(f, addr)                                                          \
    asm volatile("ldmatrix.sync.aligned.m8n8.x4.shared.b16 {%0,%1,%2,%3}, [%4];"  \
                 : "=r"((f)[0]), "=r"((f)[1]), "=r"((f)[2]), "=r"((f)[3]) : "r"(addr))

#define LDSM_X2(f, addr)                                                      \
    asm volatile("ldmatrix.sync.aligned.m8n8.x2.shared.b16 {%0,%1}, [%2];"    \
                 : "=r"((f)[0]), "=r"((f)[1]) : "r"(addr))

// ---------------- edge-index dtype detect + convert ----------------
__global__ void k_detect(const uint2* __restrict__ ei) {
    if (threadIdx.x == 0 && blockIdx.x == 0) {
        int is64 = 1;
        for (int i = 0; i < 64; i++)
            if (ei[i].y != 0u) { is64 = 0; break; }
        g_is64 = is64;
    }
}

__global__ void k_convert(const void* __restrict__ ei) {
    int e = blockIdx.x * blockDim.x + threadIdx.x;
    if (e >= Ee) return;
    int s, d;
    if (g_is64) {
        const long long* p = (const long long*)ei;
        s = (int)p[e];
        d = (int)p[e + Ee];
    } else {
        const int* p = (const int*)ei;
        s = p[e];
        d = p[e + Ee];
    }
    g_src[e] = min(max(s, 0), Nn - 1);
    g_dst[e] = min(max(d, 0), Nn - 1);
}

// ---------------- degree / normalization ----------------
__global__ void k_deg_init() {
    int i = blockIdx.x * blockDim.x + threadIdx.x;
    if (i < Nn) g_deg[i] = 1.0f;
}
__global__ void k_deg_acc() {
    int e = blockIdx.x * blockDim.x + threadIdx.x;
    if (e < Ee) atomicAdd(&g_deg[g_dst[e]], 1.0f);
}
__global__ void k_dinv() {
    int i = blockIdx.x * blockDim.x + threadIdx.x;
    if (i < Nn) g_dinv[i] = rsqrtf(g_deg[i]);
}
__global__ void k_edge_nrm() {
    int e = blockIdx.x * blockDim.x + threadIdx.x;
    if (e < Ee) g_nrm[e] = g_dinv[g_src[e]] * g_dinv[g_dst[e]];
}

// ---------------- aggregation ----------------
template<int F>
__global__ void k_self_init(const float* __restrict__ in, float* __restrict__ out) {
    int idx = blockIdx.x * blockDim.x + threadIdx.x;
    if (idx >= Nn * (F / 4)) return;
    int row = idx / (F / 4);
    float s = g_dinv[row]; s = s * s;
    float4 v = ((const float4*)in)[idx];
    v.x *= s; v.y *= s; v.z *= s; v.w *= s;
    ((float4*)out)[idx] = v;
}

template<int F>
__global__ void k_scatter(const float* __restrict__ in, float* __restrict__ out) {
    int e = (blockIdx.x * blockDim.x + threadIdx.x) >> 5;
    if (e >= Ee) return;
    int lane = threadIdx.x & 31;
    int s = g_src[e];
    int d = g_dst[e];
    float nrm = g_nrm[e];
    const float* rin  = in  + (size_t)s * F;
    float*       rout = out + (size_t)d * F;
#pragma unroll
    for (int j = lane; j < F; j += 32)
        atomicAdd(&rout[j], __ldg(&rin[j]) * nrm);
}

// ---------------- BatchNorm ----------------
__global__ void k_bn_zero() {
    int f = threadIdx.x;
    if (f < DH) { g_sum[f] = 0.0f; g_sumsq[f] = 0.0f; }
}

template<int F, int RPB>
__global__ void k_bn_stats(const float* __restrict__ h) {
    int f  = threadIdx.x;
    int r0 = blockIdx.x * RPB;
    int r1 = min(r0 + RPB, Nn);
    float s = 0.0f, ss = 0.0f;
    for (int r = r0; r < r1; ++r) {
        float v = h[(size_t)r * F + f];
        s += v; ss += v * v;
    }
    atomicAdd(&g_sum[f],   s);
    atomicAdd(&g_sumsq[f], ss);
}

__global__ void k_bn_final(const float* __restrict__ g, const float* __restrict__ be) {
    int f = threadIdx.x;
    if (f >= DH) return;
    float mu  = g_sum[f]   * (1.0f / Nn);
    float var = g_sumsq[f] * (1.0f / Nn) - mu * mu;
    float sc  = g[f] * rsqrtf(var + BNEPS);
    g_scale[f] = sc;
    g_shift[f] = be[f] - mu * sc;
}

template<bool RES>
__global__ void k_bn_apply(const float* __restrict__ h,
                           const float* __restrict__ res,
                           float* __restrict__ out) {
    int idx = blockIdx.x * blockDim.x + threadIdx.x;
    if (idx >= Nn * (DH / 4)) return;
    int f4 = idx & (DH / 4 - 1);
    float4 v  = ((const float4*)h)[idx];
    float4 sc = ((const float4*)g_scale)[f4];
    float4 sh = ((const float4*)g_shift)[f4];
    v.x = fmaxf(v.x * sc.x + sh.x, 0.0f);
    v.y = fmaxf(v.y * sc.y + sh.y, 0.0f);
    v.z = fmaxf(v.z * sc.z + sh.z, 0.0f);
    v.w = fmaxf(v.w * sc.w + sh.w, 0.0f);
    if (RES) {
        float4 r = ((const float4*)res)[idx];
        v.x += r.x; v.y += r.y; v.z += r.z; v.w += r.w;
    }
    ((float4*)out)[idx] = v;
}

// ---------------- final epilogue init: M2*dinv^2 + b2 + x ----------------
__global__ void k_final_init(const float* __restrict__ m2,
                             const float* __restrict__ x,
                             const float* __restrict__ b2,
                             float* __restrict__ out) {
    int idx = blockIdx.x * blockDim.x + threadIdx.x;
    if (idx >= Nn * (DOUT / 4)) return;
    int row = idx / (DOUT / 4);
    int c4  = idx & (DOUT / 4 - 1);
    float s = g_dinv[row]; s = s * s;
    float4 m  = ((const float4*)m2)[idx];
    float4 xx = ((const float4*)x)[idx];
    float4 b  = ((const float4*)b2)[c4];
    m.x = m.x * s + xx.x + b.x;
    m.y = m.y * s + xx.y + b.y;
    m.z = m.z * s + xx.z + b.z;
    m.w = m.w * s + xx.w + b.w;
    ((float4*)out)[idx] = m;
}

// ---------------- weight split: W[K][Nc] -> Bh/Bl planes [Nc][K] -----------
__global__ void k_cvtB(const float* __restrict__ W, __nv_bfloat16* __restrict__ out,
                       int K, int Nc) {
    int idx = blockIdx.x * blockDim.x + threadIdx.x;   // over K*Nc
    if (idx >= K * Nc) return;
    int k = idx / Nc, n = idx - k * Nc;
    float v = W[idx];
    __nv_bfloat16 h = __float2bfloat16(v);
    __nv_bfloat16 l = __float2bfloat16(v - __bfloat162float(h));
    out[(size_t)n * K + k]                   = h;
    out[(size_t)Nc * K + (size_t)n * K + k]  = l;
}

// ---------------- fused-split mma.sync GEMM ---------------------------------
// C[M x NcT] = A[M x K](fp32) * W, W pre-split as Bh/Bl planes [NcT][K] bf16.
// CTA tile 128x128, 8 warps (2x4), warp tile 64x32, chunk = 32 fp32 K.
// Per chunk: 3 MMA products AhBh + AlBh + AhBl. Register double-buffered loads.
#define LDPE 40
#define GEMM_PREFETCH(kc)                                                         \
    {                                                                             \
        _Pragma("unroll")                                                         \
        for (int it = 0; it < 4; it++) {                                          \
            int u = tid + it * 256, r = u >> 3, c4 = u & 7;                       \
            int gr = brow + r;                                                    \
            pa[it] = (gr < Nn)                                                    \
                ? *(const float4*)(A + (size_t)gr * K + (kc) + c4 * 4)            \
                : make_float4(0.f, 0.f, 0.f, 0.f);                                \
        }                                                                         \
        _Pragma("unroll")                                                         \
        for (int it = 0; it < 2; it++) {                                          \
            int u = tid + it * 256, r = u >> 2, c8 = u & 3;                       \
            const __nv_bfloat16* bp = B2 + (size_t)(bcol + r) * K + (kc) + c8 * 8;\
            pbh[it] = *(const uint4*)bp;                                          \
            pbl[it] = *(const uint4*)(bp + (size_t)NcT * K);                      \
        }                                                                         \
    }

#define GEMM_COMMIT()                                                             \
    {                                                                             \
        _Pragma("unroll")                                                         \
        for (int it = 0; it < 4; it++) {                                          \
            int u = tid + it * 256, r = u >> 3, c4 = u & 7;                       \
            float vv[4] = {pa[it].x, pa[it].y, pa[it].z, pa[it].w};               \
            __nv_bfloat16 hh[4], ll[4];                                           \
            _Pragma("unroll")                                                     \
            for (int q = 0; q < 4; q++) {                                         \
                hh[q] = __float2bfloat16(vv[q]);                                  \
                ll[q] = __float2bfloat16(vv[q] - __bfloat162float(hh[q]));        \
            }                                                                     \
            *(uint2*)&sAh[r][c4 * 4] = *(uint2*)hh;                               \
            *(uint2*)&sAl[r][c4 * 4] = *(uint2*)ll;                               \
        }                                                                         \
        _Pragma("unroll")                                                         \
        for (int it = 0; it < 2; it++) {                                          \
            int u = tid + it * 256, r = u >> 2, c8 = u & 3;                       \
            *(uint4*)&sBh[r][c8 * 8] = pbh[it];                                   \
            *(uint4*)&sBl[r][c8 * 8] = pbl[it];                                   \
        }                                                                         \
    }

template<int K>
__global__ void __launch_bounds__(256)
k_gemmF(const float* __restrict__ A, const __nv_bfloat16* __restrict__ B2,
        float* __restrict__ C, int NcT) {
    __shared__ __align__(16) __nv_bfloat16 sAh[128][LDPE];
    __shared__ __align__(16) __nv_bfloat16 sAl[128][LDPE];
    __shared__ __align__(16) __nv_bfloat16 sBh[128][LDPE];
    __shared__ __align__(16) __nv_bfloat16 sBl[128][LDPE];

    int tid  = threadIdx.x;
    int wid  = tid >> 5;
    int lane = tid & 31;
    int brow = blockIdx.y * 128;
    int bcol = blockIdx.x * 128;

    int warp_m = wid >> 2;
    int warp_n = wid & 3;
    int m_base = warp_m * 64;
    int n_base = warp_n * 32;

    float acc[4][4][4];
#pragma unroll
    for (int i = 0; i < 4; i++)
#pragma unroll
        for (int j = 0; j < 4; j++)
#pragma unroll
            for (int q = 0; q < 4; q++) acc[i][j][q] = 0.0f;

    float4 pa[4];
    uint4  pbh[2], pbl[2];

    GEMM_PREFETCH(0);
    constexpr int NCH = K / 32;
    for (int c = 0; c < NCH; c++) {
        GEMM_COMMIT();
        __syncthreads();
        if (c + 1 < NCH) GEMM_PREFETCH((c + 1) * 32);

#pragma unroll
        for (int ks = 0; ks < 2; ks++) {
            uint32_t ah[4][4], al[4][4];
#pragma unroll
            for (int i = 0; i < 4; i++) {
                int rr = m_base + i * 16 + (lane & 15);
                int cc = ks * 16 + (lane >> 4) * 8;
                uint32_t ad = smem_u32(&sAh[rr][cc]);
                LDSM_X4(ah[i], ad);
                ad = smem_u32(&sAl[rr][cc]);
                LDSM_X4(al[i], ad);
            }
#pragma unroll
            for (int j = 0; j < 4; j++) {
                int rr = n_base + j * 8 + (lane & 7);
                int cc = ks * 16 + ((lane >> 3) & 1) * 8;
                uint32_t bh2[2], bl2[2];
                uint32_t bd = smem_u32(&sBh[rr][cc]);
                LDSM_X2(bh2, bd);
                bd = smem_u32(&sBl[rr][cc]);
                LDSM_X2(bl2, bd);
#pragma unroll
                for (int i = 0; i < 4; i++) {
                    MMA16816(acc[i][j], ah[i], bh2);
                    MMA16816(acc[i][j], al[i], bh2);
                    MMA16816(acc[i][j], ah[i], bl2);
                }
            }
        }
        __syncthreads();
    }

#pragma unroll
    for (int i = 0; i < 4; i++) {
        int row0 = brow + m_base + i * 16 + (lane >> 2);
        int row1 = row0 + 8;
#pragma unroll
        for (int j = 0; j < 4; j++) {
            int col = bcol + n_base + j * 8 + (lane & 3) * 2;
            if (row0 < Nn)
                *(float2*)(C + (size_t)row0 * NcT + col) =
                    make_float2(acc[i][j][0], acc[i][j][1]);
            if (row1 < Nn)
                *(float2*)(C + (size_t)row1 * NcT + col) =
                    make_float2(acc[i][j][2], acc[i][j][3]);
        }
    }
}

// ---------------- launch ----------------
extern "C" void kernel_launch(void* const* d_in, const int* in_sizes, int n_in,
                              void* d_out, int out_size) {
    const float* x  = (const float*)d_in[0];
    const void*  ei = d_in[1];
    const float* W0 = (const float*)d_in[2];
    // b0 = d_in[3]  (cancels exactly through BatchNorm)
    const float* g0  = (const float*)d_in[4];
    const float* be0 = (const float*)d_in[5];
    const float* W1  = (const float*)d_in[6];
    // b1 = d_in[7]  (cancels exactly through BatchNorm)
    const float* g1  = (const float*)d_in[8];
    const float* be1 = (const float*)d_in[9];
    const float* W2  = (const float*)d_in[10];
    const float* b2  = (const float*)d_in[11];
    float* out = (float*)d_out;

    float *bufA, *bufB, *bufC;
    __nv_bfloat16* B16;
    cudaGetSymbolAddress((void**)&bufA, g_bufA);
    cudaGetSymbolAddress((void**)&bufB, g_bufB);
    cudaGetSymbolAddress((void**)&bufC, g_bufC);
    cudaGetSymbolAddress((void**)&B16,  g_B16);

    const int TB = 256;
    int gridE1 = (Ee + TB - 1) / TB;
    int gridN1 = (Nn + TB - 1) / TB;

    k_detect  <<<1, 32>>>((const uint2*)ei);
    k_convert <<<gridE1, TB>>>(ei);
    k_deg_init<<<gridN1, TB>>>();
    k_deg_acc <<<gridE1, TB>>>();
    k_dinv    <<<gridN1, TB>>>();
    k_edge_nrm<<<gridE1, TB>>>();

    int gridN128 = (Nn * (DIN / 4) + TB - 1) / TB;
    int gridN256 = (Nn * (DH  / 4) + TB - 1) / TB;
    int gridE    = (Ee * 32 + TB - 1) / TB;
    dim3 gemmG2(2, NPAD / 128);   // Nc=256
    dim3 gemmG1(1, NPAD / 128);   // Nc=128

    // ---- layer 0: aggregate-first on x (K=128, Nc=256) ----
    k_self_init<DIN><<<gridN128, TB>>>(x, bufA);
    k_scatter<DIN>  <<<gridE, TB>>>(x, bufA);
    k_cvtB<<<(DIN * DH + TB - 1) / TB, TB>>>(W0, B16, DIN, DH);
    k_gemmF<DIN><<<gemmG2, 256>>>(bufA, B16, bufB, DH);        // H0 = (A x) W0
    k_bn_zero<<<1, 256>>>();
    k_bn_stats<DH, 64><<<(Nn + 63) / 64, DH>>>(bufB);
    k_bn_final<<<1, 256>>>(g0, be0);
    k_bn_apply<false><<<gridN256, TB>>>(bufB, nullptr, bufA);  // h1 -> bufA

    // ---- layer 1 (K=256, Nc=256) ----
    k_self_init<DH><<<gridN256, TB>>>(bufA, bufC);
    k_scatter<DH>  <<<gridE, TB>>>(bufA, bufC);
    k_cvtB<<<(DH * DH + TB - 1) / TB, TB>>>(W1, B16, DH, DH);
    k_gemmF<DH><<<gemmG2, 256>>>(bufC, B16, bufB, DH);         // M1 = (A h1) W1
    k_bn_zero<<<1, 256>>>();
    k_bn_stats<DH, 64><<<(Nn + 63) / 64, DH>>>(bufB);
    k_bn_final<<<1, 256>>>(g1, be1);
    k_bn_apply<true><<<gridN256, TB>>>(bufB, bufA, bufC);      // h2 -> bufC

    // ---- layer 2: transform-first (K=256, Nc=128), scatter epilogue ----
    k_cvtB<<<(DH * DOUT + TB - 1) / TB, TB>>>(W2, B16, DH, DOUT);
    k_gemmF<DH><<<gemmG1, 256>>>(bufC, B16, bufA, DOUT);       // M2 = h2 W2
    k_final_init<<<gridN128, TB>>>(bufA, x, b2, out);          // M2*dinv^2 + b2 + x
    k_scatter<DOUT><<<gridE, TB>>>(bufA, out);
}

// round 8
// speedup vs baseline: 2.1550x; 1.2574x over previous
#include <cuda_runtime.h>
#include <cuda_bf16.h>
#include <cstdint>

#define Nn   50000
#define NPAD 50048
#define Ee   800000
#define DIN  128
#define DH   256
#define DOUT 128
#define BNEPS 1e-5f

// ---------------- scratch (device globals: allocation-free) ----------------
__device__ int   g_is64;
__device__ __align__(256) int   g_src [Ee];
__device__ __align__(256) int   g_dst [Ee];
__device__ __align__(256) int   g_nb_src[Ee];
__device__ __align__(256) float g_nb_nrm[Ee];
__device__ __align__(256) int   g_rowptr[Nn + 1];
__device__ __align__(256) int   g_cursor[Nn];
__device__ __align__(256) int   g_cnt [Nn];
__device__ __align__(256) float g_dinv[Nn];
__device__ __align__(256) float g_bufA[(size_t)Nn * DH];
__device__ __align__(256) float g_bufB[(size_t)Nn * DH];
__device__ __align__(256) float g_bufC[(size_t)Nn * DH];
__device__ __align__(256) __nv_bfloat16 g_W0s[(size_t)2 * DIN * DH];
__device__ __align__(256) __nv_bfloat16 g_W1s[(size_t)2 * DH * DH];
__device__ __align__(256) __nv_bfloat16 g_W2s[(size_t)2 * DH * DOUT];
__device__ __align__(256) float g_sum0  [DH];
__device__ __align__(256) float g_sumsq0[DH];
__device__ __align__(256) float g_sum1  [DH];
__device__ __align__(256) float g_sumsq1[DH];
__device__ __align__(256) float g_scale0[DH];
__device__ __align__(256) float g_shift0[DH];
__device__ __align__(256) float g_scale1[DH];
__device__ __align__(256) float g_shift1[DH];

__device__ __forceinline__ uint32_t smem_u32(const void* p) {
    uint32_t a;
    asm("{ .reg .u64 t; cvta.to.shared.u64 t, %1; cvt.u32.u64 %0, t; }" : "=r"(a) : "l"(p));
    return a;
}

#define MMA16816(d, a, b)                                                     \
    asm volatile("mma.sync.aligned.m16n8k16.row.col.f32.bf16.bf16.f32 "       \
                 "{%0,%1,%2,%3}, {%4,%5,%6,%7}, {%8,%9}, {%0,%1,%2,%3};"      \
                 : "+f"((d)[0]), "+f"((d)[1]), "+f"((d)[2]), "+f"((d)[3])     \
                 : "r"((a)[0]), "r"((a)[1]), "r"((a)[2]), "r"((a)[3]),        \
                   "r"((b)[0]), "r"((b)[1]))

#define LDSM_X4(f, addr)                                                          \
    asm volatile("ldmatrix.sync.aligned.m8n8.x4.shared.b16 {%0,%1,%2,%3}, [%4];"  \
                 : "=r"((f)[0]), "=r"((f)[1]), "=r"((f)[2]), "=r"((f)[3]) : "r"(addr))

#define LDSM_X2(f, addr)                                                      \
    asm volatile("ldmatrix.sync.aligned.m8n8.x2.shared.b16 {%0,%1}, [%2];"    \
                 : "=r"((f)[0]), "=r"((f)[1]) : "r"(addr))

__device__ __forceinline__ float4 bnrelu4(float4 t, float4 sc, float4 sh) {
    t.x = fmaxf(fmaf(t.x, sc.x, sh.x), 0.0f);
    t.y = fmaxf(fmaf(t.y, sc.y, sh.y), 0.0f);
    t.z = fmaxf(fmaf(t.z, sc.z, sh.z), 0.0f);
    t.w = fmaxf(fmaf(t.w, sc.w, sh.w), 0.0f);
    return t;
}
__device__ __forceinline__ void fma4(float4& a, float4 t, float w) {
    a.x = fmaf(t.x, w, a.x); a.y = fmaf(t.y, w, a.y);
    a.z = fmaf(t.z, w, a.z); a.w = fmaf(t.w, w, a.w);
}

// ---------------- edge-index dtype detect + convert ----------------
__global__ void k_detect(const uint2* __restrict__ ei) {
    if (threadIdx.x == 0 && blockIdx.x == 0) {
        int is64 = 1;
        for (int i = 0; i < 64; i++)
            if (ei[i].y != 0u) { is64 = 0; break; }
        g_is64 = is64;
    }
}

__global__ void k_convert(const void* __restrict__ ei) {
    int e = blockIdx.x * blockDim.x + threadIdx.x;
    if (e >= Ee) return;
    int s, d;
    if (g_is64) {
        const long long* p = (const long long*)ei;
        s = (int)p[e];
        d = (int)p[e + Ee];
    } else {
        const int* p = (const int*)ei;
        s = p[e];
        d = p[e + Ee];
    }
    g_src[e] = min(max(s, 0), Nn - 1);
    g_dst[e] = min(max(d, 0), Nn - 1);
    if (e < Nn) g_cnt[e] = 0;
}

__global__ void k_count() {
    int e = blockIdx.x * blockDim.x + threadIdx.x;
    if (e < Ee) atomicAdd(&g_cnt[g_dst[e]], 1);
}

// single-block scan over g_cnt -> rowptr/cursor; also writes dinv
__global__ void k_scan() {
    __shared__ int sh[1024];
    const int T = 1024;
    const int chunk = (Nn + T - 1) / T;
    int tid  = threadIdx.x;
    int base = tid * chunk;
    int s = 0;
    for (int j = 0; j < chunk; j++) {
        int i = base + j;
        if (i < Nn) s += g_cnt[i];
    }
    sh[tid] = s;
    __syncthreads();
    for (int off = 1; off < T; off <<= 1) {
        int v = (tid >= off) ? sh[tid - off] : 0;
        __syncthreads();
        sh[tid] += v;
        __syncthreads();
    }
    int run = sh[tid] - s;
    for (int j = 0; j < chunk; j++) {
        int i = base + j;
        if (i < Nn) {
            int c = g_cnt[i];
            g_rowptr[i] = run;
            g_cursor[i] = run;
            g_dinv[i]   = rsqrtf((float)(c + 1));
            run += c;
        }
    }
    if (tid == 0) g_rowptr[Nn] = Ee;
}

__global__ void k_fill() {
    int e = blockIdx.x * blockDim.x + threadIdx.x;
    if (e >= Ee) return;
    int s = g_src[e];
    int d = g_dst[e];
    int pos = atomicAdd(&g_cursor[d], 1);
    g_nb_src[pos] = s;
    g_nb_nrm[pos] = g_dinv[s] * g_dinv[d];
}

// ---------------- gather aggregation: one warp per node --------------------
// MODE 0: out[n] = dinv2*in[n] + sum w*in[s]
// MODE 1: same but every read of in is relu(in*scale+shift)   (BN on the fly)
// MODE 2: out[n] = dinv2*in[n] + x[n] + b2 + sum w*in[s]      (final epilogue)
template<int F, int MODE>
__global__ void __launch_bounds__(256)
k_gather(const float* __restrict__ in, const float* __restrict__ xres,
         const float* __restrict__ b2,
         const float* __restrict__ scale, const float* __restrict__ shift,
         float* __restrict__ out) {
    int n = (blockIdx.x * blockDim.x + threadIdx.x) >> 5;
    if (n >= Nn) return;
    int lane = threadIdx.x & 31;
    constexpr int V = F / 128;

    float4 sc[V], sh[V];
    if (MODE == 1) {
#pragma unroll
        for (int v = 0; v < V; v++) {
            sc[v] = ((const float4*)scale)[lane + 32 * v];
            sh[v] = ((const float4*)shift)[lane + 32 * v];
        }
    }
    float di = g_dinv[n], s2 = di * di;
    float4 acc[V];
    {
        const float4* rn = (const float4*)(in + (size_t)n * F);
#pragma unroll
        for (int v = 0; v < V; v++) {
            float4 t = __ldg(&rn[lane + 32 * v]);
            if (MODE == 1) t = bnrelu4(t, sc[v], sh[v]);
            acc[v] = make_float4(t.x * s2, t.y * s2, t.z * s2, t.w * s2);
        }
    }
    if (MODE == 2) {
        const float4* xr = (const float4*)(xres + (size_t)n * F);
#pragma unroll
        for (int v = 0; v < V; v++) {
            float4 xx = __ldg(&xr[lane + 32 * v]);
            float4 bb = __ldg(&((const float4*)b2)[lane + 32 * v]);
            acc[v].x += xx.x + bb.x;
            acc[v].y += xx.y + bb.y;
            acc[v].z += xx.z + bb.z;
            acc[v].w += xx.w + bb.w;
        }
    }

    int e   = g_rowptr[n];
    int end = g_rowptr[n + 1];
    for (; e + 4 <= end; e += 4) {
        int i0 = __ldg(&g_nb_src[e]);
        int i1 = __ldg(&g_nb_src[e + 1]);
        int i2 = __ldg(&g_nb_src[e + 2]);
        int i3 = __ldg(&g_nb_src[e + 3]);
        float w0 = __ldg(&g_nb_nrm[e]);
        float w1 = __ldg(&g_nb_nrm[e + 1]);
        float w2 = __ldg(&g_nb_nrm[e + 2]);
        float w3 = __ldg(&g_nb_nrm[e + 3]);
        const float4* r0 = (const float4*)(in + (size_t)i0 * F) + lane;
        const float4* r1 = (const float4*)(in + (size_t)i1 * F) + lane;
        const float4* r2 = (const float4*)(in + (size_t)i2 * F) + lane;
        const float4* r3 = (const float4*)(in + (size_t)i3 * F) + lane;
#pragma unroll
        for (int v = 0; v < V; v++) {
            float4 t0 = __ldg(r0 + 32 * v);
            float4 t1 = __ldg(r1 + 32 * v);
            float4 t2 = __ldg(r2 + 32 * v);
            float4 t3 = __ldg(r3 + 32 * v);
            if (MODE == 1) {
                t0 = bnrelu4(t0, sc[v], sh[v]);
                t1 = bnrelu4(t1, sc[v], sh[v]);
                t2 = bnrelu4(t2, sc[v], sh[v]);
                t3 = bnrelu4(t3, sc[v], sh[v]);
            }
            fma4(acc[v], t0, w0);
            fma4(acc[v], t1, w1);
            fma4(acc[v], t2, w2);
            fma4(acc[v], t3, w3);
        }
    }
    for (; e < end; e++) {
        int   s = __ldg(&g_nb_src[e]);
        float w = __ldg(&g_nb_nrm[e]);
        const float4* r = (const float4*)(in + (size_t)s * F) + lane;
#pragma unroll
        for (int v = 0; v < V; v++) {
            float4 t = __ldg(r + 32 * v);
            if (MODE == 1) t = bnrelu4(t, sc[v], sh[v]);
            fma4(acc[v], t, w);
        }
    }

    float4* o = (float4*)(out + (size_t)n * F);
#pragma unroll
    for (int v = 0; v < V; v++) o[lane + 32 * v] = acc[v];
}

// ---------------- BN helpers ----------------
__global__ void k_bn_zero_all() {
    int f = threadIdx.x;
    if (f < DH) {
        g_sum0[f] = 0.0f; g_sumsq0[f] = 0.0f;
        g_sum1[f] = 0.0f; g_sumsq1[f] = 0.0f;
    }
}

__global__ void k_bn_final(const float* __restrict__ g, const float* __restrict__ be,
                           const float* __restrict__ sum, const float* __restrict__ sumsq,
                           float* __restrict__ scale, float* __restrict__ shift) {
    int f = threadIdx.x;
    if (f >= DH) return;
    float mu  = sum[f]   * (1.0f / Nn);
    float var = sumsq[f] * (1.0f / Nn) - mu * mu;
    float sc  = g[f] * rsqrtf(var + BNEPS);
    scale[f] = sc;
    shift[f] = be[f] - mu * sc;
}

// h2 = relu(bn1(M1)) + relu(bn0(H0))
__global__ void k_bn_apply2(const float* __restrict__ m1, const float* __restrict__ h0,
                            float* __restrict__ out) {
    int idx = blockIdx.x * blockDim.x + threadIdx.x;
    if (idx >= Nn * (DH / 4)) return;
    int f4 = idx & (DH / 4 - 1);
    float4 a  = ((const float4*)m1)[idx];
    float4 b  = ((const float4*)h0)[idx];
    float4 s1 = ((const float4*)g_scale1)[f4];
    float4 t1 = ((const float4*)g_shift1)[f4];
    float4 s0 = ((const float4*)g_scale0)[f4];
    float4 t0 = ((const float4*)g_shift0)[f4];
    a = bnrelu4(a, s1, t1);
    b = bnrelu4(b, s0, t0);
    a.x += b.x; a.y += b.y; a.z += b.z; a.w += b.w;
    ((float4*)out)[idx] = a;
}

// ---------------- weight split: W[K][Nc] -> Bh/Bl planes [Nc][K] -----------
__global__ void k_cvtB(const float* __restrict__ W, __nv_bfloat16* __restrict__ out,
                       int K, int Nc) {
    int idx = blockIdx.x * blockDim.x + threadIdx.x;
    if (idx >= K * Nc) return;
    int k = idx / Nc, n = idx - k * Nc;
    float v = W[idx];
    __nv_bfloat16 h = __float2bfloat16(v);
    __nv_bfloat16 l = __float2bfloat16(v - __bfloat162float(h));
    out[(size_t)n * K + k]                  = h;
    out[(size_t)Nc * K + (size_t)n * K + k] = l;
}

// ---------------- fused-split mma.sync GEMM ---------------------------------
#define LDPE 40
#define GEMM_PREFETCH(kc)                                                         \
    {                                                                             \
        _Pragma("unroll")                                                         \
        for (int it = 0; it < 4; it++) {                                          \
            int u = tid + it * 256, r = u >> 3, c4 = u & 7;                       \
            int gr = brow + r;                                                    \
            pa[it] = (gr < Nn)                                                    \
                ? *(const float4*)(A + (size_t)gr * K + (kc) + c4 * 4)            \
                : make_float4(0.f, 0.f, 0.f, 0.f);                                \
        }                                                                         \
        _Pragma("unroll")                                                         \
        for (int it = 0; it < 2; it++) {                                          \
            int u = tid + it * 256, r = u >> 2, c8 = u & 3;                       \
            const __nv_bfloat16* bp = B2 + (size_t)(bcol + r) * K + (kc) + c8 * 8;\
            pbh[it] = *(const uint4*)bp;                                          \
            pbl[it] = *(const uint4*)(bp + (size_t)NcT * K);                      \
        }                                                                         \
    }

#define GEMM_COMMIT()                                                             \
    {                                                                             \
        _Pragma("unroll")                                                         \
        for (int it = 0; it < 4; it++) {                                          \
            int u = tid + it * 256, r = u >> 3, c4 = u & 7;                       \
            float vv[4] = {pa[it].x, pa[it].y, pa[it].z, pa[it].w};               \
            __nv_bfloat16 hh[4], ll[4];                                           \
            _Pragma("unroll")                                                     \
            for (int q = 0; q < 4; q++) {                                         \
                hh[q] = __float2bfloat16(vv[q]);                                  \
                ll[q] = __float2bfloat16(vv[q] - __bfloat162float(hh[q]));        \
            }                                                                     \
            *(uint2*)&sAh[r][c4 * 4] = *(uint2*)hh;                               \
            *(uint2*)&sAl[r][c4 * 4] = *(uint2*)ll;                               \
        }                                                                         \
        _Pragma("unroll")                                                         \
        for (int it = 0; it < 2; it++) {                                          \
            int u = tid + it * 256, r = u >> 2, c8 = u & 3;                       \
            *(uint4*)&sBh[r][c8 * 8] = pbh[it];                                   \
            *(uint4*)&sBl[r][c8 * 8] = pbl[it];                                   \
        }                                                                         \
    }

template<int K, bool STATS>
__global__ void __launch_bounds__(256)
k_gemmF(const float* __restrict__ A, const __nv_bfloat16* __restrict__ B2,
        float* __restrict__ C, int NcT,
        float* __restrict__ sumP, float* __restrict__ sumsqP) {
    __shared__ __align__(16) __nv_bfloat16 sAh[128][LDPE];
    __shared__ __align__(16) __nv_bfloat16 sAl[128][LDPE];
    __shared__ __align__(16) __nv_bfloat16 sBh[128][LDPE];
    __shared__ __align__(16) __nv_bfloat16 sBl[128][LDPE];

    int tid  = threadIdx.x;
    int wid  = tid >> 5;
    int lane = tid & 31;
    int brow = blockIdx.y * 128;
    int bcol = blockIdx.x * 128;

    int warp_m = wid >> 2;
    int warp_n = wid & 3;
    int m_base = warp_m * 64;
    int n_base = warp_n * 32;

    float acc[4][4][4];
#pragma unroll
    for (int i = 0; i < 4; i++)
#pragma unroll
        for (int j = 0; j < 4; j++)
#pragma unroll
            for (int q = 0; q < 4; q++) acc[i][j][q] = 0.0f;

    float4 pa[4];
    uint4  pbh[2], pbl[2];

    GEMM_PREFETCH(0);
    constexpr int NCH = K / 32;
    for (int c = 0; c < NCH; c++) {
        GEMM_COMMIT();
        __syncthreads();
        if (c + 1 < NCH) GEMM_PREFETCH((c + 1) * 32);

#pragma unroll
        for (int ks = 0; ks < 2; ks++) {
            uint32_t ah[4][4], al[4][4];
#pragma unroll
            for (int i = 0; i < 4; i++) {
                int rr = m_base + i * 16 + (lane & 15);
                int cc = ks * 16 + (lane >> 4) * 8;
                uint32_t ad = smem_u32(&sAh[rr][cc]);
                LDSM_X4(ah[i], ad);
                ad = smem_u32(&sAl[rr][cc]);
                LDSM_X4(al[i], ad);
            }
#pragma unroll
            for (int j = 0; j < 4; j++) {
                int rr = n_base + j * 8 + (lane & 7);
                int cc = ks * 16 + ((lane >> 3) & 1) * 8;
                uint32_t bh2[2], bl2[2];
                uint32_t bd = smem_u32(&sBh[rr][cc]);
                LDSM_X2(bh2, bd);
                bd = smem_u32(&sBl[rr][cc]);
                LDSM_X2(bl2, bd);
#pragma unroll
                for (int i = 0; i < 4; i++) {
                    MMA16816(acc[i][j], ah[i], bh2);
                    MMA16816(acc[i][j], al[i], bh2);
                    MMA16816(acc[i][j], ah[i], bl2);
                }
            }
        }
        __syncthreads();
    }

    // write C
#pragma unroll
    for (int i = 0; i < 4; i++) {
        int row0 = brow + m_base + i * 16 + (lane >> 2);
        int row1 = row0 + 8;
#pragma unroll
        for (int j = 0; j < 4; j++) {
            int col = bcol + n_base + j * 8 + (lane & 3) * 2;
            if (row0 < Nn)
                *(float2*)(C + (size_t)row0 * NcT + col) =
                    make_float2(acc[i][j][0], acc[i][j][1]);
            if (row1 < Nn)
                *(float2*)(C + (size_t)row1 * NcT + col) =
                    make_float2(acc[i][j][2], acc[i][j][3]);
        }
    }

    // fused BN column stats (rows < Nn only)
    if (STATS) {
#pragma unroll
        for (int j = 0; j < 4; j++) {
            float s0 = 0.f, q0 = 0.f, s1 = 0.f, q1 = 0.f;
#pragma unroll
            for (int i = 0; i < 4; i++) {
                int r0 = brow + m_base + i * 16 + (lane >> 2);
                int r1 = r0 + 8;
                float v00 = (r0 < Nn) ? acc[i][j][0] : 0.f;
                float v01 = (r0 < Nn) ? acc[i][j][1] : 0.f;
                float v10 = (r1 < Nn) ? acc[i][j][2] : 0.f;
                float v11 = (r1 < Nn) ? acc[i][j][3] : 0.f;
                s0 += v00 + v10; q0 += v00 * v00 + v10 * v10;
                s1 += v01 + v11; q1 += v01 * v01 + v11 * v11;
            }
#pragma unroll
            for (int m = 4; m <= 16; m <<= 1) {
                s0 += __shfl_xor_sync(0xFFFFFFFFu, s0, m);
                q0 += __shfl_xor_sync(0xFFFFFFFFu, q0, m);
                s1 += __shfl_xor_sync(0xFFFFFFFFu, s1, m);
                q1 += __shfl_xor_sync(0xFFFFFFFFu, q1, m);
            }
            if (lane < 4) {
                int col = bcol + n_base + j * 8 + lane * 2;
                atomicAdd(&sumP[col],       s0);
                atomicAdd(&sumsqP[col],     q0);
                atomicAdd(&sumP[col + 1],   s1);
                atomicAdd(&sumsqP[col + 1], q1);
            }
        }
    }
}

// ---------------- launch ----------------
extern "C" void kernel_launch(void* const* d_in, const int* in_sizes, int n_in,
                              void* d_out, int out_size) {
    const float* x  = (const float*)d_in[0];
    const void*  ei = d_in[1];
    const float* W0 = (const float*)d_in[2];
    // b0 = d_in[3]  (cancels exactly through BatchNorm)
    const float* g0  = (const float*)d_in[4];
    const float* be0 = (const float*)d_in[5];
    const float* W1  = (const float*)d_in[6];
    // b1 = d_in[7]  (cancels exactly through BatchNorm)
    const float* g1  = (const float*)d_in[8];
    const float* be1 = (const float*)d_in[9];
    const float* W2  = (const float*)d_in[10];
    const float* b2  = (const float*)d_in[11];
    float* out = (float*)d_out;

    float *bufA, *bufB, *bufC;
    __nv_bfloat16 *W0s, *W1s, *W2s;
    float *sum0, *sumsq0, *sum1, *sumsq1, *scale0, *shift0, *scale1, *shift1;
    cudaGetSymbolAddress((void**)&bufA, g_bufA);
    cudaGetSymbolAddress((void**)&bufB, g_bufB);
    cudaGetSymbolAddress((void**)&bufC, g_bufC);
    cudaGetSymbolAddress((void**)&W0s,  g_W0s);
    cudaGetSymbolAddress((void**)&W1s,  g_W1s);
    cudaGetSymbolAddress((void**)&W2s,  g_W2s);
    cudaGetSymbolAddress((void**)&sum0,   g_sum0);
    cudaGetSymbolAddress((void**)&sumsq0, g_sumsq0);
    cudaGetSymbolAddress((void**)&sum1,   g_sum1);
    cudaGetSymbolAddress((void**)&sumsq1, g_sumsq1);
    cudaGetSymbolAddress((void**)&scale0, g_scale0);
    cudaGetSymbolAddress((void**)&shift0, g_shift0);
    cudaGetSymbolAddress((void**)&scale1, g_scale1);
    cudaGetSymbolAddress((void**)&shift1, g_shift1);

    const int TB = 256;
    int gridE1 = (Ee + TB - 1) / TB;
    int gridW  = (Nn * 32 + TB - 1) / TB;    // 1 warp / node
    int gridN256 = (Nn * (DH / 4) + TB - 1) / TB;
    dim3 gemmG2(2, NPAD / 128);   // Nc=256
    dim3 gemmG1(1, NPAD / 128);   // Nc=128

    // setup: dtype detect, CSR build, weight splits, stat zero
    k_detect <<<1, 32>>>((const uint2*)ei);
    k_convert<<<gridE1, TB>>>(ei);
    k_count  <<<gridE1, TB>>>();
    k_scan   <<<1, 1024>>>();
    k_fill   <<<gridE1, TB>>>();
    k_cvtB<<<(DIN * DH  + TB - 1) / TB, TB>>>(W0, W0s, DIN, DH);
    k_cvtB<<<(DH  * DH  + TB - 1) / TB, TB>>>(W1, W1s, DH, DH);
    k_cvtB<<<(DH  * DOUT + TB - 1) / TB, TB>>>(W2, W2s, DH, DOUT);
    k_bn_zero_all<<<1, 256>>>();

    // ---- layer 0 ----
    k_gather<DIN, 0><<<gridW, TB>>>(x, nullptr, nullptr, nullptr, nullptr, bufA);
    k_gemmF<DIN, true><<<gemmG2, 256>>>(bufA, W0s, bufB, DH, sum0, sumsq0);  // H0
    k_bn_final<<<1, 256>>>(g0, be0, sum0, sumsq0, scale0, shift0);

    // ---- layer 1: gather applies relu(bn0(.)) on the fly ----
    k_gather<DH, 1><<<gridW, TB>>>(bufB, nullptr, nullptr, scale0, shift0, bufC);
    k_gemmF<DH, true><<<gemmG2, 256>>>(bufC, W1s, bufA, DH, sum1, sumsq1);   // M1
    k_bn_final<<<1, 256>>>(g1, be1, sum1, sumsq1, scale1, shift1);
    k_bn_apply2<<<gridN256, TB>>>(bufA, bufB, bufC);   // h2 = relu(bn1(M1))+relu(bn0(H0))

    // ---- layer 2: transform-first, epilogue fused into final gather ----
    k_gemmF<DH, false><<<gemmG1, 256>>>(bufC, W2s, bufA, DOUT, nullptr, nullptr); // M2
    k_gather<DOUT, 2><<<gridW, TB>>>(bufA, x, b2, nullptr, nullptr, out);
}

// round 9
// speedup vs baseline: 2.7362x; 1.2697x over previous
#include <cuda_runtime.h>
#include <cuda_bf16.h>
#include <cstdint>

#define Nn   50000
#define NPAD 50048
#define Ee   800000
#define DIN  128
#define DH   256
#define DOUT 128
#define BNEPS 1e-5f
#define SCANB 196          // ceil(Nn/256)

// ---------------- scratch (device globals: allocation-free) ----------------
__device__ int   g_is64;
__device__ __align__(256) int   g_src [Ee];
__device__ __align__(256) int   g_dst [Ee];
__device__ __align__(256) int   g_nb_src[Ee];
__device__ __align__(256) float g_nb_nrm[Ee];
__device__ __align__(256) int   g_rowptr[Nn + 1];
__device__ __align__(256) int   g_cursor[Nn];
__device__ __align__(256) int   g_cnt [Nn];
__device__ __align__(256) int   g_blksum[SCANB];
__device__ __align__(256) int   g_blkoff[SCANB];
__device__ __align__(256) float g_dinv[Nn];
__device__ __align__(256) float g_bufA[(size_t)Nn * DH];
__device__ __align__(256) float g_bufB[(size_t)Nn * DH];
__device__ __align__(256) float g_bufC[(size_t)Nn * DH];
__device__ __align__(256) __nv_bfloat16 g_W0s[(size_t)2 * DIN * DH];
__device__ __align__(256) __nv_bfloat16 g_W1s[(size_t)2 * DH * DH];
__device__ __align__(256) __nv_bfloat16 g_W2s[(size_t)2 * DH * DOUT];
__device__ __align__(256) float g_sum0  [DH];
__device__ __align__(256) float g_sumsq0[DH];
__device__ __align__(256) float g_sum1  [DH];
__device__ __align__(256) float g_sumsq1[DH];
__device__ __align__(256) float g_scale0[DH];
__device__ __align__(256) float g_shift0[DH];
__device__ __align__(256) float g_scale1[DH];
__device__ __align__(256) float g_shift1[DH];

__device__ __forceinline__ uint32_t smem_u32(const void* p) {
    uint32_t a;
    asm("{ .reg .u64 t; cvta.to.shared.u64 t, %1; cvt.u32.u64 %0, t; }" : "=r"(a) : "l"(p));
    return a;
}

#define MMA16816(d, a, b)                                                     \
    asm volatile("mma.sync.aligned.m16n8k16.row.col.f32.bf16.bf16.f32 "       \
                 "{%0,%1,%2,%3}, {%4,%5,%6,%7}, {%8,%9}, {%0,%1,%2,%3};"      \
                 : "+f"((d)[0]), "+f"((d)[1]), "+f"((d)[2]), "+f"((d)[3])     \
                 : "r"((a)[0]), "r"((a)[1]), "r"((a)[2]), "r"((a)[3]),        \
                   "r"((b)[0]), "r"((b)[1]))

#define LDSM_X4(f, addr)                                                          \
    asm volatile("ldmatrix.sync.aligned.m8n8.x4.shared.b16 {%0,%1,%2,%3}, [%4];"  \
                 : "=r"((f)[0]), "=r"((f)[1]), "=r"((f)[2]), "=r"((f)[3]) : "r"(addr))

#define LDSM_X2(f, addr)                                                      \
    asm volatile("ldmatrix.sync.aligned.m8n8.x2.shared.b16 {%0,%1}, [%2];"    \
                 : "=r"((f)[0]), "=r"((f)[1]) : "r"(addr))

__device__ __forceinline__ float4 bnrelu4(float4 t, float4 sc, float4 sh) {
    t.x = fmaxf(fmaf(t.x, sc.x, sh.x), 0.0f);
    t.y = fmaxf(fmaf(t.y, sc.y, sh.y), 0.0f);
    t.z = fmaxf(fmaf(t.z, sc.z, sh.z), 0.0f);
    t.w = fmaxf(fmaf(t.w, sc.w, sh.w), 0.0f);
    return t;
}
__device__ __forceinline__ void fma4(float4& a, float4 t, float w) {
    a.x = fmaf(t.x, w, a.x); a.y = fmaf(t.y, w, a.y);
    a.z = fmaf(t.z, w, a.z); a.w = fmaf(t.w, w, a.w);
}

// ---------------- edge-index dtype detect + convert ----------------
__global__ void k_detect(const uint2* __restrict__ ei) {
    if (threadIdx.x == 0 && blockIdx.x == 0) {
        int is64 = 1;
        for (int i = 0; i < 64; i++)
            if (ei[i].y != 0u) { is64 = 0; break; }
        g_is64 = is64;
    }
}

__global__ void k_convert(const void* __restrict__ ei) {
    int e = blockIdx.x * blockDim.x + threadIdx.x;
    if (e >= Ee) return;
    int s, d;
    if (g_is64) {
        const long long* p = (const long long*)ei;
        s = (int)p[e];
        d = (int)p[e + Ee];
    } else {
        const int* p = (const int*)ei;
        s = p[e];
        d = p[e + Ee];
    }
    g_src[e] = min(max(s, 0), Nn - 1);
    g_dst[e] = min(max(d, 0), Nn - 1);
    if (e < Nn) g_cnt[e] = 0;
}

__global__ void k_count() {
    int e = blockIdx.x * blockDim.x + threadIdx.x;
    if (e < Ee) atomicAdd(&g_cnt[g_dst[e]], 1);
}

// ---------------- parallel 3-phase scan over g_cnt -------------------------
__global__ void k_scan1() {               // block-reduce 256-chunks
    __shared__ int sh[256];
    int i = blockIdx.x * 256 + threadIdx.x;
    int v = (i < Nn) ? g_cnt[i] : 0;
    sh[threadIdx.x] = v;
    __syncthreads();
#pragma unroll
    for (int off = 128; off > 0; off >>= 1) {
        if (threadIdx.x < off) sh[threadIdx.x] += sh[threadIdx.x + off];
        __syncthreads();
    }
    if (threadIdx.x == 0) g_blksum[blockIdx.x] = sh[0];
}

__global__ void k_scan2() {               // scan block sums + zero BN stats
    __shared__ int sh[256];
    int t = threadIdx.x;
    int v = (t < SCANB) ? g_blksum[t] : 0;
    sh[t] = v;
    __syncthreads();
#pragma unroll
    for (int off = 1; off < 256; off <<= 1) {
        int u = (t >= off) ? sh[t - off] : 0;
        __syncthreads();
        sh[t] += u;
        __syncthreads();
    }
    if (t < SCANB) g_blkoff[t] = sh[t] - v;   // exclusive
    if (t < DH) {
        g_sum0[t] = 0.0f; g_sumsq0[t] = 0.0f;
        g_sum1[t] = 0.0f; g_sumsq1[t] = 0.0f;
    }
}

__global__ void k_scan3() {               // in-block scan + offset -> rowptr
    __shared__ int sh[256];
    int t = threadIdx.x;
    int i = blockIdx.x * 256 + t;
    int c = (i < Nn) ? g_cnt[i] : 0;
    sh[t] = c;
    __syncthreads();
#pragma unroll
    for (int off = 1; off < 256; off <<= 1) {
        int u = (t >= off) ? sh[t - off] : 0;
        __syncthreads();
        sh[t] += u;
        __syncthreads();
    }
    if (i < Nn) {
        int pre = g_blkoff[blockIdx.x] + sh[t] - c;   // exclusive prefix
        g_rowptr[i] = pre;
        g_cursor[i] = pre;
        g_dinv[i]   = rsqrtf((float)(c + 1));
    }
    if (i == Nn - 1) g_rowptr[Nn] = Ee;
}

__global__ void k_fill() {
    int e = blockIdx.x * blockDim.x + threadIdx.x;
    if (e >= Ee) return;
    int s = g_src[e];
    int d = g_dst[e];
    int pos = atomicAdd(&g_cursor[d], 1);
    g_nb_src[pos] = s;
    g_nb_nrm[pos] = g_dinv[s] * g_dinv[d];
}

// ---------------- gather aggregation: one warp per node --------------------
// MODE 0: out[n] = dinv2*in[n] + sum w*in[s]
// MODE 1: same but every read of in is relu(in*scale+shift)   (BN on the fly)
// MODE 2: out[n] = dinv2*in[n] + x[n] + b2 + sum w*in[s]      (final epilogue)
template<int F, int MODE>
__global__ void __launch_bounds__(256)
k_gather(const float* __restrict__ in, const float* __restrict__ xres,
         const float* __restrict__ b2,
         const float* __restrict__ scale, const float* __restrict__ shift,
         float* __restrict__ out) {
    int n = (blockIdx.x * blockDim.x + threadIdx.x) >> 5;
    if (n >= Nn) return;
    int lane = threadIdx.x & 31;
    constexpr int V = F / 128;

    float4 sc[V], sh[V];
    if (MODE == 1) {
#pragma unroll
        for (int v = 0; v < V; v++) {
            sc[v] = ((const float4*)scale)[lane + 32 * v];
            sh[v] = ((const float4*)shift)[lane + 32 * v];
        }
    }
    float di = g_dinv[n], s2 = di * di;
    float4 acc[V];
    {
        const float4* rn = (const float4*)(in + (size_t)n * F);
#pragma unroll
        for (int v = 0; v < V; v++) {
            float4 t = __ldg(&rn[lane + 32 * v]);
            if (MODE == 1) t = bnrelu4(t, sc[v], sh[v]);
            acc[v] = make_float4(t.x * s2, t.y * s2, t.z * s2, t.w * s2);
        }
    }
    if (MODE == 2) {
        const float4* xr = (const float4*)(xres + (size_t)n * F);
#pragma unroll
        for (int v = 0; v < V; v++) {
            float4 xx = __ldg(&xr[lane + 32 * v]);
            float4 bb = __ldg(&((const float4*)b2)[lane + 32 * v]);
            acc[v].x += xx.x + bb.x;
            acc[v].y += xx.y + bb.y;
            acc[v].z += xx.z + bb.z;
            acc[v].w += xx.w + bb.w;
        }
    }

    int e   = g_rowptr[n];
    int end = g_rowptr[n + 1];
    for (; e + 4 <= end; e += 4) {
        int i0 = __ldg(&g_nb_src[e]);
        int i1 = __ldg(&g_nb_src[e + 1]);
        int i2 = __ldg(&g_nb_src[e + 2]);
        int i3 = __ldg(&g_nb_src[e + 3]);
        float w0 = __ldg(&g_nb_nrm[e]);
        float w1 = __ldg(&g_nb_nrm[e + 1]);
        float w2 = __ldg(&g_nb_nrm[e + 2]);
        float w3 = __ldg(&g_nb_nrm[e + 3]);
        const float4* r0 = (const float4*)(in + (size_t)i0 * F) + lane;
        const float4* r1 = (const float4*)(in + (size_t)i1 * F) + lane;
        const float4* r2 = (const float4*)(in + (size_t)i2 * F) + lane;
        const float4* r3 = (const float4*)(in + (size_t)i3 * F) + lane;
#pragma unroll
        for (int v = 0; v < V; v++) {
            float4 t0 = __ldg(r0 + 32 * v);
            float4 t1 = __ldg(r1 + 32 * v);
            float4 t2 = __ldg(r2 + 32 * v);
            float4 t3 = __ldg(r3 + 32 * v);
            if (MODE == 1) {
                t0 = bnrelu4(t0, sc[v], sh[v]);
                t1 = bnrelu4(t1, sc[v], sh[v]);
                t2 = bnrelu4(t2, sc[v], sh[v]);
                t3 = bnrelu4(t3, sc[v], sh[v]);
            }
            fma4(acc[v], t0, w0);
            fma4(acc[v], t1, w1);
            fma4(acc[v], t2, w2);
            fma4(acc[v], t3, w3);
        }
    }
    for (; e < end; e++) {
        int   s = __ldg(&g_nb_src[e]);
        float w = __ldg(&g_nb_nrm[e]);
        const float4* r = (const float4*)(in + (size_t)s * F) + lane;
#pragma unroll
        for (int v = 0; v < V; v++) {
            float4 t = __ldg(r + 32 * v);
            if (MODE == 1) t = bnrelu4(t, sc[v], sh[v]);
            fma4(acc[v], t, w);
        }
    }

    float4* o = (float4*)(out + (size_t)n * F);
#pragma unroll
    for (int v = 0; v < V; v++) o[lane + 32 * v] = acc[v];
}

// ---------------- BN helpers ----------------
__global__ void k_bn_final(const float* __restrict__ g, const float* __restrict__ be,
                           const float* __restrict__ sum, const float* __restrict__ sumsq,
                           float* __restrict__ scale, float* __restrict__ shift) {
    int f = threadIdx.x;
    if (f >= DH) return;
    float mu  = sum[f]   * (1.0f / Nn);
    float var = sumsq[f] * (1.0f / Nn) - mu * mu;
    float sc  = g[f] * rsqrtf(var + BNEPS);
    scale[f] = sc;
    shift[f] = be[f] - mu * sc;
}

// h2 = relu(bn1(M1)) + relu(bn0(H0))
__global__ void k_bn_apply2(const float* __restrict__ m1, const float* __restrict__ h0,
                            float* __restrict__ out) {
    int idx = blockIdx.x * blockDim.x + threadIdx.x;
    if (idx >= Nn * (DH / 4)) return;
    int f4 = idx & (DH / 4 - 1);
    float4 a  = ((const float4*)m1)[idx];
    float4 b  = ((const float4*)h0)[idx];
    float4 s1 = ((const float4*)g_scale1)[f4];
    float4 t1 = ((const float4*)g_shift1)[f4];
    float4 s0 = ((const float4*)g_scale0)[f4];
    float4 t0 = ((const float4*)g_shift0)[f4];
    a = bnrelu4(a, s1, t1);
    b = bnrelu4(b, s0, t0);
    a.x += b.x; a.y += b.y; a.z += b.z; a.w += b.w;
    ((float4*)out)[idx] = a;
}

// ---------------- weight split: W[K][Nc] -> Bh/Bl planes [Nc][K] -----------
__global__ void k_cvtB(const float* __restrict__ W, __nv_bfloat16* __restrict__ out,
                       int K, int Nc) {
    int idx = blockIdx.x * blockDim.x + threadIdx.x;
    if (idx >= K * Nc) return;
    int k = idx / Nc, n = idx - k * Nc;
    float v = W[idx];
    __nv_bfloat16 h = __float2bfloat16(v);
    __nv_bfloat16 l = __float2bfloat16(v - __bfloat162float(h));
    out[(size_t)n * K + k]                  = h;
    out[(size_t)Nc * K + (size_t)n * K + k] = l;
}

// ---------------- fused-split mma.sync GEMM ---------------------------------
#define LDPE 40
#define GEMM_PREFETCH(kc)                                                         \
    {                                                                             \
        _Pragma("unroll")                                                         \
        for (int it = 0; it < 4; it++) {                                          \
            int u = tid + it * 256, r = u >> 3, c4 = u & 7;                       \
            int gr = brow + r;                                                    \
            pa[it] = (gr < Nn)                                                    \
                ? *(const float4*)(A + (size_t)gr * K + (kc) + c4 * 4)            \
                : make_float4(0.f, 0.f, 0.f, 0.f);                                \
        }                                                                         \
        _Pragma("unroll")                                                         \
        for (int it = 0; it < 2; it++) {                                          \
            int u = tid + it * 256, r = u >> 2, c8 = u & 3;                       \
            const __nv_bfloat16* bp = B2 + (size_t)(bcol + r) * K + (kc) + c8 * 8;\
            pbh[it] = *(const uint4*)bp;                                          \
            pbl[it] = *(const uint4*)(bp + (size_t)NcT * K);                      \
        }                                                                         \
    }

#define GEMM_COMMIT()                                                             \
    {                                                                             \
        _Pragma("unroll")                                                         \
        for (int it = 0; it < 4; it++) {                                          \
            int u = tid + it * 256, r = u >> 3, c4 = u & 7;                       \
            float vv[4] = {pa[it].x, pa[it].y, pa[it].z, pa[it].w};               \
            __nv_bfloat16 hh[4], ll[4];                                           \
            _Pragma("unroll")                                                     \
            for (int q = 0; q < 4; q++) {                                         \
                hh[q] = __float2bfloat16(vv[q]);                                  \
                ll[q] = __float2bfloat16(vv[q] - __bfloat162float(hh[q]));        \
            }                                                                     \
            *(uint2*)&sAh[r][c4 * 4] = *(uint2*)hh;                               \
            *(uint2*)&sAl[r][c4 * 4] = *(uint2*)ll;                               \
        }                                                                         \
        _Pragma("unroll")                                                         \
        for (int it = 0; it < 2; it++) {                                          \
            int u = tid + it * 256, r = u >> 2, c8 = u & 3;                       \
            *(uint4*)&sBh[r][c8 * 8] = pbh[it];                                   \
            *(uint4*)&sBl[r][c8 * 8] = pbl[it];                                   \
        }                                                                         \
    }

template<int K, bool STATS>
__global__ void __launch_bounds__(256)
k_gemmF(const float* __restrict__ A, const __nv_bfloat16* __restrict__ B2,
        float* __restrict__ C, int NcT,
        float* __restrict__ sumP, float* __restrict__ sumsqP) {
    __shared__ __align__(16) __nv_bfloat16 sAh[128][LDPE];
    __shared__ __align__(16) __nv_bfloat16 sAl[128][LDPE];
    __shared__ __align__(16) __nv_bfloat16 sBh[128][LDPE];
    __shared__ __align__(16) __nv_bfloat16 sBl[128][LDPE];

    int tid  = threadIdx.x;
    int wid  = tid >> 5;
    int lane = tid & 31;
    int brow = blockIdx.y * 128;
    int bcol = blockIdx.x * 128;

    int warp_m = wid >> 2;
    int warp_n = wid & 3;
    int m_base = warp_m * 64;
    int n_base = warp_n * 32;

    float acc[4][4][4];
#pragma unroll
    for (int i = 0; i < 4; i++)
#pragma unroll
        for (int j = 0; j < 4; j++)
#pragma unroll
            for (int q = 0; q < 4; q++) acc[i][j][q] = 0.0f;

    float4 pa[4];
    uint4  pbh[2], pbl[2];

    GEMM_PREFETCH(0);
    constexpr int NCH = K / 32;
    for (int c = 0; c < NCH; c++) {
        GEMM_COMMIT();
        __syncthreads();
        if (c + 1 < NCH) GEMM_PREFETCH((c + 1) * 32);

#pragma unroll
        for (int ks = 0; ks < 2; ks++) {
            uint32_t ah[4][4], al[4][4];
#pragma unroll
            for (int i = 0; i < 4; i++) {
                int rr = m_base + i * 16 + (lane & 15);
                int cc = ks * 16 + (lane >> 4) * 8;
                uint32_t ad = smem_u32(&sAh[rr][cc]);
                LDSM_X4(ah[i], ad);
                ad = smem_u32(&sAl[rr][cc]);
                LDSM_X4(al[i], ad);
            }
#pragma unroll
            for (int j = 0; j < 4; j++) {
                int rr = n_base + j * 8 + (lane & 7);
                int cc = ks * 16 + ((lane >> 3) & 1) * 8;
                uint32_t bh2[2], bl2[2];
                uint32_t bd = smem_u32(&sBh[rr][cc]);
                LDSM_X2(bh2, bd);
                bd = smem_u32(&sBl[rr][cc]);
                LDSM_X2(bl2, bd);
#pragma unroll
                for (int i = 0; i < 4; i++) {
                    MMA16816(acc[i][j], ah[i], bh2);
                    MMA16816(acc[i][j], al[i], bh2);
                    MMA16816(acc[i][j], ah[i], bl2);
                }
            }
        }
        __syncthreads();
    }

    // write C
#pragma unroll
    for (int i = 0; i < 4; i++) {
        int row0 = brow + m_base + i * 16 + (lane >> 2);
        int row1 = row0 + 8;
#pragma unroll
        for (int j = 0; j < 4; j++) {
            int col = bcol + n_base + j * 8 + (lane & 3) * 2;
            if (row0 < Nn)
                *(float2*)(C + (size_t)row0 * NcT + col) =
                    make_float2(acc[i][j][0], acc[i][j][1]);
            if (row1 < Nn)
                *(float2*)(C + (size_t)row1 * NcT + col) =
                    make_float2(acc[i][j][2], acc[i][j][3]);
        }
    }

    // fused BN column stats (rows < Nn only)
    if (STATS) {
#pragma unroll
        for (int j = 0; j < 4; j++) {
            float s0 = 0.f, q0 = 0.f, s1 = 0.f, q1 = 0.f;
#pragma unroll
            for (int i = 0; i < 4; i++) {
                int r0 = brow + m_base + i * 16 + (lane >> 2);
                int r1 = r0 + 8;
                float v00 = (r0 < Nn) ? acc[i][j][0] : 0.f;
                float v01 = (r0 < Nn) ? acc[i][j][1] : 0.f;
                float v10 = (r1 < Nn) ? acc[i][j][2] : 0.f;
                float v11 = (r1 < Nn) ? acc[i][j][3] : 0.f;
                s0 += v00 + v10; q0 += v00 * v00 + v10 * v10;
                s1 += v01 + v11; q1 += v01 * v01 + v11 * v11;
            }
#pragma unroll
            for (int m = 4; m <= 16; m <<= 1) {
                s0 += __shfl_xor_sync(0xFFFFFFFFu, s0, m);
                q0 += __shfl_xor_sync(0xFFFFFFFFu, q0, m);
                s1 += __shfl_xor_sync(0xFFFFFFFFu, s1, m);
                q1 += __shfl_xor_sync(0xFFFFFFFFu, q1, m);
            }
            if (lane < 4) {
                int col = bcol + n_base + j * 8 + lane * 2;
                atomicAdd(&sumP[col],       s0);
                atomicAdd(&sumsqP[col],     q0);
                atomicAdd(&sumP[col + 1],   s1);
                atomicAdd(&sumsqP[col + 1], q1);
            }
        }
    }
}

// ---------------- launch ----------------
extern "C" void kernel_launch(void* const* d_in, const int* in_sizes, int n_in,
                              void* d_out, int out_size) {
    const float* x  = (const float*)d_in[0];
    const void*  ei = d_in[1];
    const float* W0 = (const float*)d_in[2];
    // b0 = d_in[3]  (cancels exactly through BatchNorm)
    const float* g0  = (const float*)d_in[4];
    const float* be0 = (const float*)d_in[5];
    const float* W1  = (const float*)d_in[6];
    // b1 = d_in[7]  (cancels exactly through BatchNorm)
    const float* g1  = (const float*)d_in[8];
    const float* be1 = (const float*)d_in[9];
    const float* W2  = (const float*)d_in[10];
    const float* b2  = (const float*)d_in[11];
    float* out = (float*)d_out;

    float *bufA, *bufB, *bufC;
    __nv_bfloat16 *W0s, *W1s, *W2s;
    float *sum0, *sumsq0, *sum1, *sumsq1, *scale0, *shift0, *scale1, *shift1;
    cudaGetSymbolAddress((void**)&bufA, g_bufA);
    cudaGetSymbolAddress((void**)&bufB, g_bufB);
    cudaGetSymbolAddress((void**)&bufC, g_bufC);
    cudaGetSymbolAddress((void**)&W0s,  g_W0s);
    cudaGetSymbolAddress((void**)&W1s,  g_W1s);
    cudaGetSymbolAddress((void**)&W2s,  g_W2s);
    cudaGetSymbolAddress((void**)&sum0,   g_sum0);
    cudaGetSymbolAddress((void**)&sumsq0, g_sumsq0);
    cudaGetSymbolAddress((void**)&sum1,   g_sum1);
    cudaGetSymbolAddress((void**)&sumsq1, g_sumsq1);
    cudaGetSymbolAddress((void**)&scale0, g_scale0);
    cudaGetSymbolAddress((void**)&shift0, g_shift0);
    cudaGetSymbolAddress((void**)&scale1, g_scale1);
    cudaGetSymbolAddress((void**)&shift1, g_shift1);

    const int TB = 256;
    int gridE1 = (Ee + TB - 1) / TB;
    int gridW  = (Nn * 32 + TB - 1) / TB;    // 1 warp / node
    int gridN256 = (Nn * (DH / 4) + TB - 1) / TB;
    dim3 gemmG2(2, NPAD / 128);   // Nc=256
    dim3 gemmG1(1, NPAD / 128);   // Nc=128

    // setup: dtype detect, CSR build (parallel scan), weight splits
    k_detect <<<1, 32>>>((const uint2*)ei);
    k_convert<<<gridE1, TB>>>(ei);
    k_count  <<<gridE1, TB>>>();
    k_scan1  <<<SCANB, 256>>>();
    k_scan2  <<<1, 256>>>();
    k_scan3  <<<SCANB, 256>>>();
    k_fill   <<<gridE1, TB>>>();
    k_cvtB<<<(DIN * DH  + TB - 1) / TB, TB>>>(W0, W0s, DIN, DH);
    k_cvtB<<<(DH  * DH  + TB - 1) / TB, TB>>>(W1, W1s, DH, DH);
    k_cvtB<<<(DH  * DOUT + TB - 1) / TB, TB>>>(W2, W2s, DH, DOUT);

    // ---- layer 0 ----
    k_gather<DIN, 0><<<gridW, TB>>>(x, nullptr, nullptr, nullptr, nullptr, bufA);
    k_gemmF<DIN, true><<<gemmG2, 256>>>(bufA, W0s, bufB, DH, sum0, sumsq0);  // H0
    k_bn_final<<<1, 256>>>(g0, be0, sum0, sumsq0, scale0, shift0);

    // ---- layer 1: gather applies relu(bn0(.)) on the fly ----
    k_gather<DH, 1><<<gridW, TB>>>(bufB, nullptr, nullptr, scale0, shift0, bufC);
    k_gemmF<DH, true><<<gemmG2, 256>>>(bufC, W1s, bufA, DH, sum1, sumsq1);   // M1
    k_bn_final<<<1, 256>>>(g1, be1, sum1, sumsq1, scale1, shift1);
    k_bn_apply2<<<gridN256, TB>>>(bufA, bufB, bufC);   // h2 = relu(bn1(M1))+relu(bn0(H0))

    // ---- layer 2: transform-first, epilogue fused into final gather ----
    k_gemmF<DH, false><<<gemmG1, 256>>>(bufC, W2s, bufA, DOUT, nullptr, nullptr); // M2
    k_gather<DOUT, 2><<<gridW, TB>>>(bufA, x, b2, nullptr, nullptr, out);
}

// round 10
// speedup vs baseline: 2.7961x; 1.0219x over previous
#include <cuda_runtime.h>
#include <cuda_bf16.h>
#include <cstdint>

#define Nn   50000
#define NPAD 50048
#define Ee   800000
#define DIN  128
#define DH   256
#define DOUT 128
#define BNEPS 1e-5f
#define SCANB 196          // ceil(Nn/256)

// ---------------- scratch (device globals: allocation-free) ----------------
__device__ int   g_is64;
__device__ __align__(256) int   g_src [Ee];
__device__ __align__(256) int   g_dst [Ee];
__device__ __align__(256) int   g_nb_src[Ee];
__device__ __align__(256) float g_nb_nrm[Ee];
__device__ __align__(256) int   g_rowptr[Nn + 1];
__device__ __align__(256) int   g_cursor[Nn];
__device__ __align__(256) int   g_cnt [Nn];
__device__ __align__(256) int   g_blksum[SCANB];
__device__ __align__(256) int   g_blkoff[SCANB];
__device__ __align__(256) float g_dinv[Nn];
__device__ __align__(256) float g_bufA[(size_t)Nn * DH];
__device__ __align__(256) float g_bufB[(size_t)Nn * DH];
__device__ __align__(256) float g_bufC[(size_t)Nn * DH];
__device__ __align__(256) __nv_bfloat16 g_W0s[(size_t)2 * DIN * DH];
__device__ __align__(256) __nv_bfloat16 g_W1s[(size_t)2 * DH * DH];
__device__ __align__(256) __nv_bfloat16 g_W2s[(size_t)2 * DH * DOUT];
__device__ __align__(256) float g_sum0  [DH];
__device__ __align__(256) float g_sumsq0[DH];
__device__ __align__(256) float g_sum1  [DH];
__device__ __align__(256) float g_sumsq1[DH];
__device__ __align__(256) float g_scale0[DH];
__device__ __align__(256) float g_shift0[DH];
__device__ __align__(256) float g_scale1[DH];
__device__ __align__(256) float g_shift1[DH];

__device__ __forceinline__ uint32_t smem_u32(const void* p) {
    uint32_t a;
    asm("{ .reg .u64 t; cvta.to.shared.u64 t, %1; cvt.u32.u64 %0, t; }" : "=r"(a) : "l"(p));
    return a;
}

#define MMA16816(d, a, b)                                                     \
    asm volatile("mma.sync.aligned.m16n8k16.row.col.f32.bf16.bf16.f32 "       \
                 "{%0,%1,%2,%3}, {%4,%5,%6,%7}, {%8,%9}, {%0,%1,%2,%3};"      \
                 : "+f"((d)[0]), "+f"((d)[1]), "+f"((d)[2]), "+f"((d)[3])     \
                 : "r"((a)[0]), "r"((a)[1]), "r"((a)[2]), "r"((a)[3]),        \
                   "r"((b)[0]), "r"((b)[1]))

#define LDSM_X4(f, addr)                                                          \
    asm volatile("ldmatrix.sync.aligned.m8n8.x4.shared.b16 {%0,%1,%2,%3}, [%4];"  \
                 : "=r"((f)[0]), "=r"((f)[1]), "=r"((f)[2]), "=r"((f)[3]) : "r"(addr))

#define LDSM_X2(f, addr)                                                      \
    asm volatile("ldmatrix.sync.aligned.m8n8.x2.shared.b16 {%0,%1}, [%2];"    \
                 : "=r"((f)[0]), "=r"((f)[1]) : "r"(addr))

__device__ __forceinline__ float4 bnrelu4(float4 t, float4 sc, float4 sh) {
    t.x = fmaxf(fmaf(t.x, sc.x, sh.x), 0.0f);
    t.y = fmaxf(fmaf(t.y, sc.y, sh.y), 0.0f);
    t.z = fmaxf(fmaf(t.z, sc.z, sh.z), 0.0f);
    t.w = fmaxf(fmaf(t.w, sc.w, sh.w), 0.0f);
    return t;
}
__device__ __forceinline__ void fma4(float4& a, float4 t, float w) {
    a.x = fmaf(t.x, w, a.x); a.y = fmaf(t.y, w, a.y);
    a.z = fmaf(t.z, w, a.z); a.w = fmaf(t.w, w, a.w);
}

// ---------------- detect dtype + zero degree counters ----------------
__global__ void k_detect_zero(const uint2* __restrict__ ei) {
    int i = blockIdx.x * blockDim.x + threadIdx.x;
    if (i < Nn) g_cnt[i] = 0;
    if (i == 0) {
        int is64 = 1;
        for (int j = 0; j < 64; j++)
            if (ei[j].y != 0u) { is64 = 0; break; }
        g_is64 = is64;
    }
}

// convert + fused degree count
__global__ void k_convert(const void* __restrict__ ei) {
    int e = blockIdx.x * blockDim.x + threadIdx.x;
    if (e >= Ee) return;
    int s, d;
    if (g_is64) {
        const long long* p = (const long long*)ei;
        s = (int)p[e];
        d = (int)p[e + Ee];
    } else {
        const int* p = (const int*)ei;
        s = p[e];
        d = p[e + Ee];
    }
    s = min(max(s, 0), Nn - 1);
    d = min(max(d, 0), Nn - 1);
    g_src[e] = s;
    g_dst[e] = d;
    atomicAdd(&g_cnt[d], 1);
}

// ---------------- parallel 3-phase scan over g_cnt -------------------------
__global__ void k_scan1() {
    __shared__ int sh[256];
    int i = blockIdx.x * 256 + threadIdx.x;
    int v = (i < Nn) ? g_cnt[i] : 0;
    sh[threadIdx.x] = v;
    __syncthreads();
#pragma unroll
    for (int off = 128; off > 0; off >>= 1) {
        if (threadIdx.x < off) sh[threadIdx.x] += sh[threadIdx.x + off];
        __syncthreads();
    }
    if (threadIdx.x == 0) g_blksum[blockIdx.x] = sh[0];
}

__global__ void k_scan2() {               // scan block sums + zero BN stats
    __shared__ int sh[256];
    int t = threadIdx.x;
    int v = (t < SCANB) ? g_blksum[t] : 0;
    sh[t] = v;
    __syncthreads();
#pragma unroll
    for (int off = 1; off < 256; off <<= 1) {
        int u = (t >= off) ? sh[t - off] : 0;
        __syncthreads();
        sh[t] += u;
        __syncthreads();
    }
    if (t < SCANB) g_blkoff[t] = sh[t] - v;
    if (t < DH) {
        g_sum0[t] = 0.0f; g_sumsq0[t] = 0.0f;
        g_sum1[t] = 0.0f; g_sumsq1[t] = 0.0f;
    }
}

__global__ void k_scan3() {
    __shared__ int sh[256];
    int t = threadIdx.x;
    int i = blockIdx.x * 256 + t;
    int c = (i < Nn) ? g_cnt[i] : 0;
    sh[t] = c;
    __syncthreads();
#pragma unroll
    for (int off = 1; off < 256; off <<= 1) {
        int u = (t >= off) ? sh[t - off] : 0;
        __syncthreads();
        sh[t] += u;
        __syncthreads();
    }
    if (i < Nn) {
        int pre = g_blkoff[blockIdx.x] + sh[t] - c;
        g_rowptr[i] = pre;
        g_cursor[i] = pre;
        g_dinv[i]   = rsqrtf((float)(c + 1));
    }
    if (i == Nn - 1) g_rowptr[Nn] = Ee;
}

__global__ void k_fill() {
    int e = blockIdx.x * blockDim.x + threadIdx.x;
    if (e >= Ee) return;
    int s = g_src[e];
    int d = g_dst[e];
    int pos = atomicAdd(&g_cursor[d], 1);
    g_nb_src[pos] = s;
    g_nb_nrm[pos] = g_dinv[s] * g_dinv[d];
}

// ---------------- gather aggregation: one warp per node --------------------
// MODE 0: out[n] = dinv2*in[n] + sum w*in[s]
// MODE 1: same but every read of in is relu(in*scale+shift)
// MODE 2: out[n] = dinv2*in[n] + x[n] + b2 + sum w*in[s]
template<int F, int MODE>
__global__ void __launch_bounds__(256)
k_gather(const float* __restrict__ in, const float* __restrict__ xres,
         const float* __restrict__ b2,
         const float* __restrict__ scale, const float* __restrict__ shift,
         float* __restrict__ out) {
    int n = (blockIdx.x * blockDim.x + threadIdx.x) >> 5;
    if (n >= Nn) return;
    int lane = threadIdx.x & 31;
    constexpr int V = F / 128;

    float4 sc[V], sh[V];
    if (MODE == 1) {
#pragma unroll
        for (int v = 0; v < V; v++) {
            sc[v] = ((const float4*)scale)[lane + 32 * v];
            sh[v] = ((const float4*)shift)[lane + 32 * v];
        }
    }
    float di = g_dinv[n], s2 = di * di;
    float4 acc[V];
    {
        const float4* rn = (const float4*)(in + (size_t)n * F);
#pragma unroll
        for (int v = 0; v < V; v++) {
            float4 t = __ldg(&rn[lane + 32 * v]);
            if (MODE == 1) t = bnrelu4(t, sc[v], sh[v]);
            acc[v] = make_float4(t.x * s2, t.y * s2, t.z * s2, t.w * s2);
        }
    }
    if (MODE == 2) {
        const float4* xr = (const float4*)(xres + (size_t)n * F);
#pragma unroll
        for (int v = 0; v < V; v++) {
            float4 xx = __ldg(&xr[lane + 32 * v]);
            float4 bb = __ldg(&((const float4*)b2)[lane + 32 * v]);
            acc[v].x += xx.x + bb.x;
            acc[v].y += xx.y + bb.y;
            acc[v].z += xx.z + bb.z;
            acc[v].w += xx.w + bb.w;
        }
    }

    int e   = g_rowptr[n];
    int end = g_rowptr[n + 1];
    for (; e + 4 <= end; e += 4) {
        int i0 = __ldg(&g_nb_src[e]);
        int i1 = __ldg(&g_nb_src[e + 1]);
        int i2 = __ldg(&g_nb_src[e + 2]);
        int i3 = __ldg(&g_nb_src[e + 3]);
        float w0 = __ldg(&g_nb_nrm[e]);
        float w1 = __ldg(&g_nb_nrm[e + 1]);
        float w2 = __ldg(&g_nb_nrm[e + 2]);
        float w3 = __ldg(&g_nb_nrm[e + 3]);
        const float4* r0 = (const float4*)(in + (size_t)i0 * F) + lane;
        const float4* r1 = (const float4*)(in + (size_t)i1 * F) + lane;
        const float4* r2 = (const float4*)(in + (size_t)i2 * F) + lane;
        const float4* r3 = (const float4*)(in + (size_t)i3 * F) + lane;
#pragma unroll
        for (int v = 0; v < V; v++) {
            float4 t0 = __ldg(r0 + 32 * v);
            float4 t1 = __ldg(r1 + 32 * v);
            float4 t2 = __ldg(r2 + 32 * v);
            float4 t3 = __ldg(r3 + 32 * v);
            if (MODE == 1) {
                t0 = bnrelu4(t0, sc[v], sh[v]);
                t1 = bnrelu4(t1, sc[v], sh[v]);
                t2 = bnrelu4(t2, sc[v], sh[v]);
                t3 = bnrelu4(t3, sc[v], sh[v]);
            }
            fma4(acc[v], t0, w0);
            fma4(acc[v], t1, w1);
            fma4(acc[v], t2, w2);
            fma4(acc[v], t3, w3);
        }
    }
    for (; e < end; e++) {
        int   s = __ldg(&g_nb_src[e]);
        float w = __ldg(&g_nb_nrm[e]);
        const float4* r = (const float4*)(in + (size_t)s * F) + lane;
#pragma unroll
        for (int v = 0; v < V; v++) {
            float4 t = __ldg(r + 32 * v);
            if (MODE == 1) t = bnrelu4(t, sc[v], sh[v]);
            fma4(acc[v], t, w);
        }
    }

    float4* o = (float4*)(out + (size_t)n * F);
#pragma unroll
    for (int v = 0; v < V; v++) o[lane + 32 * v] = acc[v];
}

// ---------------- BN final ----------------
__global__ void k_bn_final(const float* __restrict__ g, const float* __restrict__ be,
                           const float* __restrict__ sum, const float* __restrict__ sumsq,
                           float* __restrict__ scale, float* __restrict__ shift) {
    int f = threadIdx.x;
    if (f >= DH) return;
    float mu  = sum[f]   * (1.0f / Nn);
    float var = sumsq[f] * (1.0f / Nn) - mu * mu;
    float sc  = g[f] * rsqrtf(var + BNEPS);
    scale[f] = sc;
    shift[f] = be[f] - mu * sc;
}

// ---------------- weight split: W[K][Nc] -> Bh/Bl planes [Nc][K] -----------
__global__ void k_cvtB(const float* __restrict__ W, __nv_bfloat16* __restrict__ out,
                       int K, int Nc) {
    int idx = blockIdx.x * blockDim.x + threadIdx.x;
    if (idx >= K * Nc) return;
    int k = idx / Nc, n = idx - k * Nc;
    float v = W[idx];
    __nv_bfloat16 h = __float2bfloat16(v);
    __nv_bfloat16 l = __float2bfloat16(v - __bfloat162float(h));
    out[(size_t)n * K + k]                  = h;
    out[(size_t)Nc * K + (size_t)n * K + k] = l;
}

// ---------------- fused-split mma.sync GEMM ---------------------------------
// FUSE: A-operand computed on the fly as relu(bn1(A)) + relu(bn0(A0)).
#define LDPE 40
#define GEMM_PREFETCH(kc)                                                         \
    {                                                                             \
        _Pragma("unroll")                                                         \
        for (int it = 0; it < 4; it++) {                                          \
            int u = tid + it * 256, r = u >> 3, c4 = u & 7;                       \
            int gr = brow + r;                                                    \
            if (gr < Nn) {                                                        \
                pa[it] = *(const float4*)(A + (size_t)gr * K + (kc) + c4 * 4);    \
                if (FUSE)                                                         \
                    pa0[it] = *(const float4*)(A0 + (size_t)gr * K + (kc) + c4 * 4);\
            } else {                                                              \
                pa[it] = make_float4(0.f, 0.f, 0.f, 0.f);                         \
                if (FUSE) pa0[it] = make_float4(0.f, 0.f, 0.f, 0.f);              \
            }                                                                     \
        }                                                                         \
        _Pragma("unroll")                                                         \
        for (int it = 0; it < 2; it++) {                                          \
            int u = tid + it * 256, r = u >> 2, c8 = u & 3;                       \
            const __nv_bfloat16* bp = B2 + (size_t)(bcol + r) * K + (kc) + c8 * 8;\
            pbh[it] = *(const uint4*)bp;                                          \
            pbl[it] = *(const uint4*)(bp + (size_t)NcT * K);                      \
        }                                                                         \
    }

#define GEMM_COMMIT(kc)                                                           \
    {                                                                             \
        float4 s1v, t1v, s0v, t0v;                                                \
        if (FUSE) {                                                               \
            int cb = (kc) + (tid & 7) * 4;                                        \
            s1v = *(const float4*)(g_scale1 + cb);                                \
            t1v = *(const float4*)(g_shift1 + cb);                                \
            s0v = *(const float4*)(g_scale0 + cb);                                \
            t0v = *(const float4*)(g_shift0 + cb);                                \
        }                                                                         \
        _Pragma("unroll")                                                         \
        for (int it = 0; it < 4; it++) {                                          \
            int u = tid + it * 256, r = u >> 3, c4 = u & 7;                       \
            float4 v4 = pa[it];                                                   \
            if (FUSE) {                                                           \
                v4 = bnrelu4(v4, s1v, t1v);                                       \
                float4 w4 = bnrelu4(pa0[it], s0v, t0v);                           \
                v4.x += w4.x; v4.y += w4.y; v4.z += w4.z; v4.w += w4.w;           \
            }                                                                     \
            float vv[4] = {v4.x, v4.y, v4.z, v4.w};                               \
            __nv_bfloat16 hh[4], ll[4];                                           \
            _Pragma("unroll")                                                     \
            for (int q = 0; q < 4; q++) {                                         \
                hh[q] = __float2bfloat16(vv[q]);                                  \
                ll[q] = __float2bfloat16(vv[q] - __bfloat162float(hh[q]));        \
            }                                                                     \
            *(uint2*)&sAh[r][c4 * 4] = *(uint2*)hh;                               \
            *(uint2*)&sAl[r][c4 * 4] = *(uint2*)ll;                               \
        }                                                                         \
        _Pragma("unroll")                                                         \
        for (int it = 0; it < 2; it++) {                                          \
            int u = tid + it * 256, r = u >> 2, c8 = u & 3;                       \
            *(uint4*)&sBh[r][c8 * 8] = pbh[it];                                   \
            *(uint4*)&sBl[r][c8 * 8] = pbl[it];                                   \
        }                                                                         \
    }

template<int K, bool STATS, bool FUSE>
__global__ void __launch_bounds__(256)
k_gemmF(const float* __restrict__ A, const float* __restrict__ A0,
        const __nv_bfloat16* __restrict__ B2,
        float* __restrict__ C, int NcT,
        float* __restrict__ sumP, float* __restrict__ sumsqP) {
    __shared__ __align__(16) __nv_bfloat16 sAh[128][LDPE];
    __shared__ __align__(16) __nv_bfloat16 sAl[128][LDPE];
    __shared__ __align__(16) __nv_bfloat16 sBh[128][LDPE];
    __shared__ __align__(16) __nv_bfloat16 sBl[128][LDPE];

    int tid  = threadIdx.x;
    int wid  = tid >> 5;
    int lane = tid & 31;
    int brow = blockIdx.y * 128;
    int bcol = blockIdx.x * 128;

    int warp_m = wid >> 2;
    int warp_n = wid & 3;
    int m_base = warp_m * 64;
    int n_base = warp_n * 32;

    float acc[4][4][4];
#pragma unroll
    for (int i = 0; i < 4; i++)
#pragma unroll
        for (int j = 0; j < 4; j++)
#pragma unroll
            for (int q = 0; q < 4; q++) acc[i][j][q] = 0.0f;

    float4 pa[4], pa0[4];
    uint4  pbh[2], pbl[2];

    GEMM_PREFETCH(0);
    constexpr int NCH = K / 32;
    for (int c = 0; c < NCH; c++) {
        GEMM_COMMIT(c * 32);
        __syncthreads();
        if (c + 1 < NCH) GEMM_PREFETCH((c + 1) * 32);

#pragma unroll
        for (int ks = 0; ks < 2; ks++) {
            uint32_t ah[4][4], al[4][4];
#pragma unroll
            for (int i = 0; i < 4; i++) {
                int rr = m_base + i * 16 + (lane & 15);
                int cc = ks * 16 + (lane >> 4) * 8;
                uint32_t ad = smem_u32(&sAh[rr][cc]);
                LDSM_X4(ah[i], ad);
                ad = smem_u32(&sAl[rr][cc]);
                LDSM_X4(al[i], ad);
            }
#pragma unroll
            for (int j = 0; j < 4; j++) {
                int rr = n_base + j * 8 + (lane & 7);
                int cc = ks * 16 + ((lane >> 3) & 1) * 8;
                uint32_t bh2[2], bl2[2];
                uint32_t bd = smem_u32(&sBh[rr][cc]);
                LDSM_X2(bh2, bd);
                bd = smem_u32(&sBl[rr][cc]);
                LDSM_X2(bl2, bd);
#pragma unroll
                for (int i = 0; i < 4; i++) {
                    MMA16816(acc[i][j], ah[i], bh2);
                    MMA16816(acc[i][j], al[i], bh2);
                    MMA16816(acc[i][j], ah[i], bl2);
                }
            }
        }
        __syncthreads();
    }

    // write C
#pragma unroll
    for (int i = 0; i < 4; i++) {
        int row0 = brow + m_base + i * 16 + (lane >> 2);
        int row1 = row0 + 8;
#pragma unroll
        for (int j = 0; j < 4; j++) {
            int col = bcol + n_base + j * 8 + (lane & 3) * 2;
            if (row0 < Nn)
                *(float2*)(C + (size_t)row0 * NcT + col) =
                    make_float2(acc[i][j][0], acc[i][j][1]);
            if (row1 < Nn)
                *(float2*)(C + (size_t)row1 * NcT + col) =
                    make_float2(acc[i][j][2], acc[i][j][3]);
        }
    }

    // fused BN column stats
    if (STATS) {
#pragma unroll
        for (int j = 0; j < 4; j++) {
            float s0 = 0.f, q0 = 0.f, s1 = 0.f, q1 = 0.f;
#pragma unroll
            for (int i = 0; i < 4; i++) {
                int r0 = brow + m_base + i * 16 + (lane >> 2);
                int r1 = r0 + 8;
                float v00 = (r0 < Nn) ? acc[i][j][0] : 0.f;
                float v01 = (r0 < Nn) ? acc[i][j][1] : 0.f;
                float v10 = (r1 < Nn) ? acc[i][j][2] : 0.f;
                float v11 = (r1 < Nn) ? acc[i][j][3] : 0.f;
                s0 += v00 + v10; q0 += v00 * v00 + v10 * v10;
                s1 += v01 + v11; q1 += v01 * v01 + v11 * v11;
            }
#pragma unroll
            for (int m = 4; m <= 16; m <<= 1) {
                s0 += __shfl_xor_sync(0xFFFFFFFFu, s0, m);
                q0 += __shfl_xor_sync(0xFFFFFFFFu, q0, m);
                s1 += __shfl_xor_sync(0xFFFFFFFFu, s1, m);
                q1 += __shfl_xor_sync(0xFFFFFFFFu, q1, m);
            }
            if (lane < 4) {
                int col = bcol + n_base + j * 8 + lane * 2;
                atomicAdd(&sumP[col],       s0);
                atomicAdd(&sumsqP[col],     q0);
                atomicAdd(&sumP[col + 1],   s1);
                atomicAdd(&sumsqP[col + 1], q1);
            }
        }
    }
}

// ---------------- launch ----------------
extern "C" void kernel_launch(void* const* d_in, const int* in_sizes, int n_in,
                              void* d_out, int out_size) {
    const float* x  = (const float*)d_in[0];
    const void*  ei = d_in[1];
    const float* W0 = (const float*)d_in[2];
    // b0 = d_in[3]  (cancels exactly through BatchNorm)
    const float* g0  = (const float*)d_in[4];
    const float* be0 = (const float*)d_in[5];
    const float* W1  = (const float*)d_in[6];
    // b1 = d_in[7]  (cancels exactly through BatchNorm)
    const float* g1  = (const float*)d_in[8];
    const float* be1 = (const float*)d_in[9];
    const float* W2  = (const float*)d_in[10];
    const float* b2  = (const float*)d_in[11];
    float* out = (float*)d_out;

    float *bufA, *bufB, *bufC;
    __nv_bfloat16 *W0s, *W1s, *W2s;
    float *sum0, *sumsq0, *sum1, *sumsq1, *scale0, *shift0, *scale1, *shift1;
    cudaGetSymbolAddress((void**)&bufA, g_bufA);
    cudaGetSymbolAddress((void**)&bufB, g_bufB);
    cudaGetSymbolAddress((void**)&bufC, g_bufC);
    cudaGetSymbolAddress((void**)&W0s,  g_W0s);
    cudaGetSymbolAddress((void**)&W1s,  g_W1s);
    cudaGetSymbolAddress((void**)&W2s,  g_W2s);
    cudaGetSymbolAddress((void**)&sum0,   g_sum0);
    cudaGetSymbolAddress((void**)&sumsq0, g_sumsq0);
    cudaGetSymbolAddress((void**)&sum1,   g_sum1);
    cudaGetSymbolAddress((void**)&sumsq1, g_sumsq1);
    cudaGetSymbolAddress((void**)&scale0, g_scale0);
    cudaGetSymbolAddress((void**)&shift0, g_shift0);
    cudaGetSymbolAddress((void**)&scale1, g_scale1);
    cudaGetSymbolAddress((void**)&shift1, g_shift1);

    const int TB = 256;
    int gridE1 = (Ee + TB - 1) / TB;
    int gridN1 = (Nn + TB - 1) / TB;
    int gridW  = (Nn * 32 + TB - 1) / TB;    // 1 warp / node
    dim3 gemmG2(2, NPAD / 128);   // Nc=256
    dim3 gemmG1(1, NPAD / 128);   // Nc=128

    // setup: dtype detect + cnt zero, convert+count, scan, fill, weight splits
    k_detect_zero<<<gridN1, TB>>>((const uint2*)ei);
    k_convert<<<gridE1, TB>>>(ei);
    k_scan1  <<<SCANB, 256>>>();
    k_scan2  <<<1, 256>>>();
    k_scan3  <<<SCANB, 256>>>();
    k_fill   <<<gridE1, TB>>>();
    k_cvtB<<<(DIN * DH  + TB - 1) / TB, TB>>>(W0, W0s, DIN, DH);
    k_cvtB<<<(DH  * DH  + TB - 1) / TB, TB>>>(W1, W1s, DH, DH);
    k_cvtB<<<(DH  * DOUT + TB - 1) / TB, TB>>>(W2, W2s, DH, DOUT);

    // ---- layer 0 ----
    k_gather<DIN, 0><<<gridW, TB>>>(x, nullptr, nullptr, nullptr, nullptr, bufA);
    k_gemmF<DIN, true, false><<<gemmG2, 256>>>(bufA, nullptr, W0s, bufB, DH,
                                               sum0, sumsq0);                  // H0
    k_bn_final<<<1, 256>>>(g0, be0, sum0, sumsq0, scale0, shift0);

    // ---- layer 1: gather applies relu(bn0(.)) on the fly ----
    k_gather<DH, 1><<<gridW, TB>>>(bufB, nullptr, nullptr, scale0, shift0, bufC);
    k_gemmF<DH, true, false><<<gemmG2, 256>>>(bufC, nullptr, W1s, bufA, DH,
                                              sum1, sumsq1);                   // M1
    k_bn_final<<<1, 256>>>(g1, be1, sum1, sumsq1, scale1, shift1);

    // ---- layer 2: h2 computed in-GEMM from M1(bufA) + H0(bufB) ----
    k_gemmF<DH, false, true><<<gemmG1, 256>>>(bufA, bufB, W2s, bufC, DOUT,
                                              nullptr, nullptr);               // M2
    k_gather<DOUT, 2><<<gridW, TB>>>(bufC, x, b2, nullptr, nullptr, out);
}